// round 11
// baseline (speedup 1.0000x reference)
#include <cuda_runtime.h>
#include <cuda_bf16.h>
#include <math_constants.h>
#include <cstdint>

#define BATCH 16
#define NPTS  4096
#define GPTS  1024
#define D1    128
#define D2    256
#define CIN   384
#define CH    256
#define COUT  256
#define NT    (BATCH * NPTS)      /* 65536 flat rows */
#define BN_EPS 1e-5f

#define SROW 40                    /* smem row stride in bf16 (80 B), K-chunk 32 */
#define TILEA (256 * SROW * 2)     /* A tile bytes (256 rows) = 20480 */
#define TILEB2 (128 * SROW * 2)    /* B tile bytes (128 rows) = 10240 */

// ======================= scratch (device globals) ===========================
__device__ uint4 g_X1hi[(size_t)NT * CIN / 8];   // bf16 [NT][384]
__device__ uint4 g_X1lo[(size_t)NT * CIN / 8];
__device__ uint4 g_X2hi[(size_t)NT * CH / 8];    // bf16 [NT][256]
__device__ uint4 g_X2lo[(size_t)NT * CH / 8];
__device__ float g_Y1t[(size_t)NT * CH];          // fp32 [NT][256]
__device__ float g_f2t[(size_t)BATCH * GPTS * D2];
__device__ float4 g_knnw[NT];                     // (w0,w1,w2,-)
__device__ int4   g_knni[NT];                     // (i0,i1,i2,-)
__device__ uint4 g_W1hi[CH * CIN / 8], g_W1lo[CH * CIN / 8];     // bf16 [256][384]
__device__ uint4 g_W2hi[COUT * CH / 8], g_W2lo[COUT * CH / 8];   // bf16 [256][256]
__device__ float g_sum1[CH],   g_sumsq1[CH];
__device__ float g_sum2[COUT], g_sumsq2[COUT];
__device__ float g_scale1[CH],   g_shift1[CH];
__device__ float g_scale2[COUT], g_shift2[COUT];

// ======================= asm helpers ========================================
__device__ __forceinline__ uint32_t smem_u32(const void* p) {
    uint32_t a;
    asm("{ .reg .u64 t; cvta.to.shared.u64 t, %1; cvt.u32.u64 %0, t; }"
        : "=r"(a) : "l"(p));
    return a;
}

#define CPA16(dst_u32, src_ptr) \
    asm volatile("cp.async.cg.shared.global [%0], [%1], 16;" \
                 :: "r"(dst_u32), "l"(src_ptr) : "memory")
#define CP_COMMIT() asm volatile("cp.async.commit_group;" ::: "memory")
#define CP_WAIT1()  asm volatile("cp.async.wait_group 1;" ::: "memory")
#define CP_WAIT0()  asm volatile("cp.async.wait_group 0;" ::: "memory")

__device__ __forceinline__ void mma16816(float c[4],
                                         uint32_t a0, uint32_t a1, uint32_t a2, uint32_t a3,
                                         uint32_t b0, uint32_t b1) {
    asm volatile(
        "mma.sync.aligned.m16n8k16.row.col.f32.bf16.bf16.f32 "
        "{%0,%1,%2,%3}, {%4,%5,%6,%7}, {%8,%9}, {%0,%1,%2,%3};"
        : "+f"(c[0]), "+f"(c[1]), "+f"(c[2]), "+f"(c[3])
        : "r"(a0), "r"(a1), "r"(a2), "r"(a3), "r"(b0), "r"(b1));
}

// ======================= small kernels ======================================
__global__ void init_kernel() {
    int t = threadIdx.x;
    g_sum1[t] = 0.f; g_sumsq1[t] = 0.f;
    g_sum2[t] = 0.f; g_sumsq2[t] = 0.f;
}

__device__ __forceinline__ void split1(float v, __nv_bfloat16& h, __nv_bfloat16& l) {
    h = __float2bfloat16(v);
    l = __float2bfloat16(v - __bfloat162float(h));
}

__global__ void convert_w_kernel(const float* __restrict__ W1,
                                 const float* __restrict__ W2) {
    int i = blockIdx.x * blockDim.x + threadIdx.x;
    const int t1 = CH * CIN;
    const int t2 = COUT * CH;
    if (i < t1) {
        __nv_bfloat16 h, l; split1(W1[i], h, l);
        ((__nv_bfloat16*)g_W1hi)[i] = h;
        ((__nv_bfloat16*)g_W1lo)[i] = l;
    } else if (i < t1 + t2) {
        int j = i - t1;
        __nv_bfloat16 h, l; split1(W2[j], h, l);
        ((__nv_bfloat16*)g_W2hi)[j] = h;
        ((__nv_bfloat16*)g_W2lo)[j] = l;
    }
}

// transpose feature2: [B][D2][G] -> [B][G][D2]  (fp32)
__global__ void transpose_f2_kernel(const float* __restrict__ f2) {
    __shared__ float tile[32][33];
    int b  = blockIdx.z;
    int g0 = blockIdx.x * 32;
    int d0 = blockIdx.y * 32;
    const float* src = f2 + (size_t)b * D2 * GPTS;
    #pragma unroll
    for (int r = threadIdx.y; r < 32; r += 8)
        tile[r][threadIdx.x] = src[(size_t)(d0 + r) * GPTS + g0 + threadIdx.x];
    __syncthreads();
    float* dst = g_f2t + (size_t)b * GPTS * D2;
    #pragma unroll
    for (int r = threadIdx.y; r < 32; r += 8)
        dst[(size_t)(g0 + r) * D2 + d0 + threadIdx.x] = tile[threadIdx.x][r];
}

// transpose feature1: [B][D1][N] -> X1 rows [row][0:128] (bf16 hi/lo)
__global__ void transpose_f1_kernel(const float* __restrict__ f1) {
    __shared__ float tile[32][33];
    const int b  = blockIdx.z;
    const int n0 = blockIdx.x * 32;
    const int d0 = blockIdx.y * 32;
    const float* src = f1 + (size_t)b * D1 * NPTS;
    #pragma unroll
    for (int r = threadIdx.y; r < 32; r += 8)
        tile[r][threadIdx.x] = src[(size_t)(d0 + r) * NPTS + n0 + threadIdx.x];
    __syncthreads();
    __nv_bfloat16* hi = (__nv_bfloat16*)g_X1hi;
    __nv_bfloat16* lo = (__nv_bfloat16*)g_X1lo;
    #pragma unroll
    for (int i = threadIdx.y; i < 32; i += 8) {
        const size_t row = (size_t)b * NPTS + n0 + i;
        __nv_bfloat16 h, l;
        split1(tile[threadIdx.x][i], h, l);
        hi[row * CIN + d0 + threadIdx.x] = h;
        lo[row * CIN + d0 + threadIdx.x] = l;
    }
}

__device__ __forceinline__ void split8_store(const float v[8], uint4* hip, uint4* lop) {
    uint32_t h[4], l[4];
    #pragma unroll
    for (int i = 0; i < 4; ++i) {
        __nv_bfloat16 h0, l0, h1, l1;
        split1(v[2 * i], h0, l0);
        split1(v[2 * i + 1], h1, l1);
        h[i] = (uint32_t)__bfloat16_as_ushort(h0) | ((uint32_t)__bfloat16_as_ushort(h1) << 16);
        l[i] = (uint32_t)__bfloat16_as_ushort(l0) | ((uint32_t)__bfloat16_as_ushort(l1) << 16);
    }
    *hip = make_uint4(h[0], h[1], h[2], h[3]);
    *lop = make_uint4(l[0], l[1], l[2], l[3]);
}

// 3-NN search only: 8 lanes x 2 points per group. Block 256 = 32 groups.
__global__ void knn_search_kernel(const float* __restrict__ coord1,
                                  const float* __restrict__ coord2) {
    __shared__ float4 s2[GPTS];
    const int b   = blockIdx.y;
    const int tid = threadIdx.x;
    const int q   = tid & 7;                        // lane within group
    const int nb  = blockIdx.x * 64 + (tid >> 3) * 2;   // first of 2 points

    const float* c2 = coord2 + (size_t)b * 3 * GPTS;
    for (int g = tid; g < GPTS; g += 256) {
        float x = c2[g], y = c2[GPTS + g], z = c2[2 * GPTS + g];
        s2[g] = make_float4(x, y, z, -0.5f * (x * x + y * y + z * z));
    }
    __syncthreads();

    const float* c1 = coord1 + (size_t)b * 3 * NPTS;
    float2 pxv = *(const float2*)(c1 + nb);
    float2 pyv = *(const float2*)(c1 + NPTS + nb);
    float2 pzv = *(const float2*)(c1 + 2 * NPTS + nb);
    const float px[2] = {pxv.x, pxv.y};
    const float py[2] = {pyv.x, pyv.y};
    const float pz[2] = {pzv.x, pzv.y};

    float e0[2], e1[2], e2[2];
    int   i0[2], i1[2], i2[2];
    #pragma unroll
    for (int p = 0; p < 2; ++p) {
        e0[p] = e1[p] = e2[p] = -CUDART_INF_F;
        i0[p] = i1[p] = i2[p] = 0;
    }

    #pragma unroll 4
    for (int it = 0; it < GPTS / 8; ++it) {
        const int g = q + it * 8;
        const float4 c = s2[g];
        #pragma unroll
        for (int p = 0; p < 2; ++p) {
            float e = fmaf(px[p], c.x, fmaf(py[p], c.y, fmaf(pz[p], c.z, c.w)));
            if (e > e2[p]) {
                if (e > e1[p]) {
                    e2[p] = e1[p]; i2[p] = i1[p];
                    if (e > e0[p]) { e1[p] = e0[p]; i1[p] = i0[p]; e0[p] = e; i0[p] = g; }
                    else           { e1[p] = e; i1[p] = g; }
                } else { e2[p] = e; i2[p] = g; }
            }
        }
    }

    #pragma unroll
    for (int off = 1; off <= 4; off <<= 1) {
        #pragma unroll
        for (int p = 0; p < 2; ++p) {
            float f0 = __shfl_xor_sync(0xffffffffu, e0[p], off);
            float f1 = __shfl_xor_sync(0xffffffffu, e1[p], off);
            float f2 = __shfl_xor_sync(0xffffffffu, e2[p], off);
            int   j0 = __shfl_xor_sync(0xffffffffu, i0[p], off);
            int   j1 = __shfl_xor_sync(0xffffffffu, i1[p], off);
            int   j2 = __shfl_xor_sync(0xffffffffu, i2[p], off);
            float m0, m1, m2; int k0, k1, k2;
            if (e0[p] >= f0) {
                m0 = e0[p]; k0 = i0[p];
                if (e1[p] >= f0) {
                    m1 = e1[p]; k1 = i1[p];
                    if (e2[p] >= f0) { m2 = e2[p]; k2 = i2[p]; } else { m2 = f0; k2 = j0; }
                } else {
                    m1 = f0; k1 = j0;
                    if (e1[p] >= f1) { m2 = e1[p]; k2 = i1[p]; } else { m2 = f1; k2 = j1; }
                }
            } else {
                m0 = f0; k0 = j0;
                if (f1 >= e0[p]) {
                    m1 = f1; k1 = j1;
                    if (f2 >= e0[p]) { m2 = f2; k2 = j2; } else { m2 = e0[p]; k2 = i0[p]; }
                } else {
                    m1 = e0[p]; k1 = i0[p];
                    if (f1 >= e1[p]) { m2 = f1; k2 = j1; } else { m2 = e1[p]; k2 = i1[p]; }
                }
            }
            e0[p] = m0; i0[p] = k0; e1[p] = m1; i1[p] = k1; e2[p] = m2; i2[p] = k2;
        }
    }

    if (q == 0) {
        #pragma unroll
        for (int p = 0; p < 2; ++p) {
            const float qn = px[p] * px[p] + py[p] * py[p] + pz[p] * pz[p];
            const float d0 = qn - 2.0f * e0[p];
            const float d1 = qn - 2.0f * e1[p];
            const float d2 = qn - 2.0f * e2[p];
            const float r0w = 1.0f / (d0 + 1e-8f);
            const float r1w = 1.0f / (d1 + 1e-8f);
            const float r2w = 1.0f / (d2 + 1e-8f);
            const float rs = 1.0f / (r0w + r1w + r2w);
            const size_t row = (size_t)b * NPTS + nb + p;
            g_knnw[row] = make_float4(r0w * rs, r1w * rs, r2w * rs, 0.f);
            g_knni[row] = make_int4(i0[p], i1[p], i2[p], 0);
        }
    }
}

// gather + interp: one warp per point; lane c handles interp chunk c (0..31).
__global__ void knn_gather_kernel() {
    const int gid = blockIdx.x * 256 + threadIdx.x;
    const size_t r = (size_t)(gid >> 5);      // point row
    const int c = gid & 31;                   // d8 chunk within D2
    const int b = (int)(r >> 12);

    const float4 w = g_knnw[r];
    const int4  ii = g_knni[r];
    const float* F = g_f2t + (size_t)b * GPTS * D2;
    const float4* p0 = (const float4*)(F + (size_t)ii.x * D2);
    const float4* p1 = (const float4*)(F + (size_t)ii.y * D2);
    const float4* p2 = (const float4*)(F + (size_t)ii.z * D2);

    float4 a0 = p0[2 * c], a1 = p0[2 * c + 1];
    float4 b0 = p1[2 * c], b1 = p1[2 * c + 1];
    float4 g0 = p2[2 * c], g1 = p2[2 * c + 1];
    float v[8];
    v[0] = w.x * a0.x + w.y * b0.x + w.z * g0.x;
    v[1] = w.x * a0.y + w.y * b0.y + w.z * g0.y;
    v[2] = w.x * a0.z + w.y * b0.z + w.z * g0.z;
    v[3] = w.x * a0.w + w.y * b0.w + w.z * g0.w;
    v[4] = w.x * a1.x + w.y * b1.x + w.z * g1.x;
    v[5] = w.x * a1.y + w.y * b1.y + w.z * g1.y;
    v[6] = w.x * a1.z + w.y * b1.z + w.z * g1.z;
    v[7] = w.x * a1.w + w.y * b1.w + w.z * g1.w;
    split8_store(v, g_X1hi + r * (CIN / 8) + D1 / 8 + c,
                    g_X1lo + r * (CIN / 8) + D1 / 8 + c);
}

// ======================= HMMA GEMM (M=256 CTA tile, fused split-phases) =====
// C[m][n] = Whi*Xhi + Whi*Xlo + Wlo*Xhi per K32 chunk; every X tile is read
// exactly once chip-wide. CTA: 512 threads, 16 warps = 4(M)x4(N), tile
// 256(M)x128(N), 2-stage cp.async. LAYER1 -> g_Y1t[n][m]; LAYER2 -> out.
template <int LAYER>
__global__ void __launch_bounds__(512, 1)
gemm_mma_kernel(const float* __restrict__ bias, float* __restrict__ outp) {
    constexpr int K0 = (LAYER == 1) ? CIN : CH;
    constexpr int NC = K0 / 32;

    const __nv_bfloat16* Whi = (LAYER == 1) ? (const __nv_bfloat16*)g_W1hi
                                            : (const __nv_bfloat16*)g_W2hi;
    const __nv_bfloat16* Wlo = (LAYER == 1) ? (const __nv_bfloat16*)g_W1lo
                                            : (const __nv_bfloat16*)g_W2lo;
    const __nv_bfloat16* Xhi = (LAYER == 1) ? (const __nv_bfloat16*)g_X1hi
                                            : (const __nv_bfloat16*)g_X2hi;
    const __nv_bfloat16* Xlo = (LAYER == 1) ? (const __nv_bfloat16*)g_X1lo
                                            : (const __nv_bfloat16*)g_X2lo;
    float* gsum  = (LAYER == 1) ? g_sum1 : g_sum2;
    float* gsq   = (LAYER == 1) ? g_sumsq1 : g_sumsq2;

    __shared__ __align__(16) __nv_bfloat16 sAhi[2][256 * SROW];
    __shared__ __align__(16) __nv_bfloat16 sAlo[2][256 * SROW];
    __shared__ __align__(16) __nv_bfloat16 sBhi[2][128 * SROW];
    __shared__ __align__(16) __nv_bfloat16 sBlo[2][128 * SROW];

    const int tid  = threadIdx.x;
    const int wid  = tid >> 5, lane = tid & 31;
    const int tg   = lane >> 2;            // groupID (0..7)
    const int tig  = lane & 3;             // threadID_in_group (0..3)
    const size_t r0 = (size_t)blockIdx.x * 128;   // X row block
    const int wm = (wid & 3) * 64;                // M warp offset (0..192)
    const int wn = (wid >> 2) * 32;               // N warp offset (0..96)

    const uint32_t aAhi = smem_u32(sAhi);
    const uint32_t aAlo = smem_u32(sAlo);
    const uint32_t aBhi = smem_u32(sBhi);
    const uint32_t aBlo = smem_u32(sBlo);
    const int ldr  = tid >> 2;             // load row (0..127)
    const int ldch = tid & 3;              // 16B chunk in row (32 cols = 4)
    const uint32_t ldoff = (uint32_t)(ldr * SROW * 2 + ldch * 16);

    float acc[4][4][4];
    #pragma unroll
    for (int i = 0; i < 4; ++i)
        #pragma unroll
        for (int j = 0; j < 4; ++j)
            #pragma unroll
            for (int k = 0; k < 4; ++k) acc[i][j][k] = 0.f;

    auto issue = [&](int c, int st) {
        const int kk = c * 32;
        // A tiles: 256 rows (two halves)
        #pragma unroll
        for (int i = 0; i < 2; ++i) {
            const int r = ldr + i * 128;
            const uint32_t d = (uint32_t)st * TILEA + ldoff
                             + (uint32_t)(i * 128 * SROW * 2);
            const size_t ga = (size_t)r * K0 + kk + ldch * 8;
            CPA16(aAhi + d, Whi + ga);
            CPA16(aAlo + d, Wlo + ga);
        }
        // B tiles: 128 rows
        {
            const uint32_t d = (uint32_t)st * TILEB2 + ldoff;
            const size_t gb = (r0 + ldr) * K0 + kk + ldch * 8;
            CPA16(aBhi + d, Xhi + gb);
            CPA16(aBlo + d, Xlo + gb);
        }
        CP_COMMIT();
    };

    issue(0, 0);
    for (int c = 0; c < NC; ++c) {
        const int st = c & 1;
        if (c + 1 < NC) { issue(c + 1, st ^ 1); CP_WAIT1(); }
        else            { CP_WAIT0(); }
        __syncthreads();

        const __nv_bfloat16* Ahi = sAhi[st];
        const __nv_bfloat16* Alo = sAlo[st];
        const __nv_bfloat16* Bhi = sBhi[st];
        const __nv_bfloat16* Blo = sBlo[st];
        #pragma unroll
        for (int ks = 0; ks < 2; ++ks) {      // k16 steps within 32-chunk
            const int kb = ks * 16;
            int rb[4], ra0[4], ra1[4];
            #pragma unroll
            for (int ni = 0; ni < 4; ++ni) rb[ni] = (wn + ni * 8 + tg) * SROW;
            #pragma unroll
            for (int mi = 0; mi < 4; ++mi) {
                ra0[mi] = (wm + mi * 16 + tg) * SROW;
                ra1[mi] = ra0[mi] + 8 * SROW;
            }
            uint32_t bh[4][2], ah[4][4];
            #pragma unroll
            for (int ni = 0; ni < 4; ++ni) {
                bh[ni][0] = *(const uint32_t*)(&Bhi[rb[ni] + kb + 2 * tig]);
                bh[ni][1] = *(const uint32_t*)(&Bhi[rb[ni] + kb + 8 + 2 * tig]);
            }
            #pragma unroll
            for (int mi = 0; mi < 4; ++mi) {
                ah[mi][0] = *(const uint32_t*)(&Ahi[ra0[mi] + kb + 2 * tig]);
                ah[mi][1] = *(const uint32_t*)(&Ahi[ra1[mi] + kb + 2 * tig]);
                ah[mi][2] = *(const uint32_t*)(&Ahi[ra0[mi] + kb + 8 + 2 * tig]);
                ah[mi][3] = *(const uint32_t*)(&Ahi[ra1[mi] + kb + 8 + 2 * tig]);
            }
            // phase hh: Whi * Xhi
            #pragma unroll
            for (int mi = 0; mi < 4; ++mi)
                #pragma unroll
                for (int ni = 0; ni < 4; ++ni)
                    mma16816(acc[mi][ni], ah[mi][0], ah[mi][1], ah[mi][2], ah[mi][3],
                             bh[ni][0], bh[ni][1]);
            // phase hl: Whi * Xlo (reuse ah)
            #pragma unroll
            for (int ni = 0; ni < 4; ++ni) {
                uint32_t bl0 = *(const uint32_t*)(&Blo[rb[ni] + kb + 2 * tig]);
                uint32_t bl1 = *(const uint32_t*)(&Blo[rb[ni] + kb + 8 + 2 * tig]);
                #pragma unroll
                for (int mi = 0; mi < 4; ++mi)
                    mma16816(acc[mi][ni], ah[mi][0], ah[mi][1], ah[mi][2], ah[mi][3],
                             bl0, bl1);
            }
            // phase lh: Wlo * Xhi (reuse bh)
            #pragma unroll
            for (int mi = 0; mi < 4; ++mi) {
                uint32_t al0 = *(const uint32_t*)(&Alo[ra0[mi] + kb + 2 * tig]);
                uint32_t al1 = *(const uint32_t*)(&Alo[ra1[mi] + kb + 2 * tig]);
                uint32_t al2 = *(const uint32_t*)(&Alo[ra0[mi] + kb + 8 + 2 * tig]);
                uint32_t al3 = *(const uint32_t*)(&Alo[ra1[mi] + kb + 8 + 2 * tig]);
                #pragma unroll
                for (int ni = 0; ni < 4; ++ni)
                    mma16816(acc[mi][ni], al0, al1, al2, al3, bh[ni][0], bh[ni][1]);
            }
        }
        __syncthreads();
    }

    // epilogue: store + fused BN stats
    const int bb = (int)(r0 >> 12);            // batch (LAYER2)
    const int n0 = (int)(r0 & (NPTS - 1));     // n offset within batch
    #pragma unroll
    for (int mi = 0; mi < 4; ++mi) {
        const int mg0 = wm + mi * 16 + tg;
        const int mg1 = mg0 + 8;
        const float bv0 = bias[mg0];
        const float bv1 = bias[mg1];
        float s0 = 0.f, q0 = 0.f, s1 = 0.f, q1 = 0.f;
        #pragma unroll
        for (int ni = 0; ni < 4; ++ni) {
            const float v00 = acc[mi][ni][0] + bv0;
            const float v01 = acc[mi][ni][1] + bv0;
            const float v10 = acc[mi][ni][2] + bv1;
            const float v11 = acc[mi][ni][3] + bv1;
            if (LAYER == 1) {
                const size_t n = r0 + wn + ni * 8 + 2 * tig;
                g_Y1t[n * 256 + mg0]       = v00;
                g_Y1t[(n + 1) * 256 + mg0] = v01;
                g_Y1t[n * 256 + mg1]       = v10;
                g_Y1t[(n + 1) * 256 + mg1] = v11;
            } else {
                const int nloc = n0 + wn + ni * 8 + 2 * tig;
                *(float2*)(outp + ((size_t)bb * 256 + mg0) * NPTS + nloc) =
                    make_float2(v00, v01);
                *(float2*)(outp + ((size_t)bb * 256 + mg1) * NPTS + nloc) =
                    make_float2(v10, v11);
            }
            s0 += v00 + v01; q0 += v00 * v00 + v01 * v01;
            s1 += v10 + v11; q1 += v10 * v10 + v11 * v11;
        }
        #pragma unroll
        for (int off = 1; off <= 2; off <<= 1) {
            s0 += __shfl_xor_sync(0xffffffffu, s0, off);
            q0 += __shfl_xor_sync(0xffffffffu, q0, off);
            s1 += __shfl_xor_sync(0xffffffffu, s1, off);
            q1 += __shfl_xor_sync(0xffffffffu, q1, off);
        }
        if (tig == 0) {
            atomicAdd(&gsum[mg0], s0); atomicAdd(&gsq[mg0], q0);
            atomicAdd(&gsum[mg1], s1); atomicAdd(&gsq[mg1], q1);
        }
    }
}

// ======================= finalize / fold ====================================
template <int LAYER>
__global__ void finalize_kernel(const float* __restrict__ gamma,
                                const float* __restrict__ beta) {
    const float* gsum = (LAYER == 1) ? g_sum1 : g_sum2;
    const float* gsq  = (LAYER == 1) ? g_sumsq1 : g_sumsq2;
    float* scale      = (LAYER == 1) ? g_scale1 : g_scale2;
    float* shift      = (LAYER == 1) ? g_shift1 : g_shift2;
    const int c = threadIdx.x;
    const float inv = 1.0f / (float)((size_t)NT);
    float m  = gsum[c] * inv;
    float v  = fmaxf(gsq[c] * inv - m * m, 0.f);
    float sc = gamma[c] * rsqrtf(v + BN_EPS);
    scale[c] = sc;
    shift[c] = beta[c] - m * sc;
}

// BN1 + ReLU + bf16 split: Y1t [row][256] -> X2hi/X2lo [row][256]
__global__ void convert2_kernel() {
    const int gid = blockIdx.x * 256 + threadIdx.x;       // one per 8 channels
    const size_t r = (size_t)(gid >> 5);
    const int c0 = (gid & 31) * 8;
    const float* p = g_Y1t + r * 256 + c0;
    float4 a = *(const float4*)(p);
    float4 b = *(const float4*)(p + 4);
    float4 s0 = *(const float4*)(g_scale1 + c0);
    float4 s1 = *(const float4*)(g_scale1 + c0 + 4);
    float4 t0 = *(const float4*)(g_shift1 + c0);
    float4 t1 = *(const float4*)(g_shift1 + c0 + 4);
    float v[8];
    v[0] = fmaxf(fmaf(a.x, s0.x, t0.x), 0.f);
    v[1] = fmaxf(fmaf(a.y, s0.y, t0.y), 0.f);
    v[2] = fmaxf(fmaf(a.z, s0.z, t0.z), 0.f);
    v[3] = fmaxf(fmaf(a.w, s0.w, t0.w), 0.f);
    v[4] = fmaxf(fmaf(b.x, s1.x, t1.x), 0.f);
    v[5] = fmaxf(fmaf(b.y, s1.y, t1.y), 0.f);
    v[6] = fmaxf(fmaf(b.z, s1.z, t1.z), 0.f);
    v[7] = fmaxf(fmaf(b.w, s1.w, t1.w), 0.f);
    split8_store(v, g_X2hi + (r * 256 + c0) / 8, g_X2lo + (r * 256 + c0) / 8);
}

// final: BN2 + ReLU in place on out [b][m][n]
__global__ void apply2_kernel(float* __restrict__ out) {
    const int i4 = blockIdx.x * 256 + threadIdx.x;   // float4 index
    const int c  = (i4 >> 10) & 255;                 // NPTS/4 = 1024 f4 per row
    const float s = g_scale2[c], t = g_shift2[c];
    float4 v = ((float4*)out)[i4];
    v.x = fmaxf(fmaf(v.x, s, t), 0.f);
    v.y = fmaxf(fmaf(v.y, s, t), 0.f);
    v.z = fmaxf(fmaf(v.z, s, t), 0.f);
    v.w = fmaxf(fmaf(v.w, s, t), 0.f);
    ((float4*)out)[i4] = v;
}

// ======================= launch =============================================
extern "C" void kernel_launch(void* const* d_in, const int* in_sizes, int n_in,
                              void* d_out, int out_size) {
    const float* feature1 = (const float*)d_in[0];
    const float* coord1   = (const float*)d_in[1];
    const float* feature2 = (const float*)d_in[2];
    const float* coord2   = (const float*)d_in[3];
    const float* W1 = (const float*)d_in[4];
    const float* b1 = (const float*)d_in[5];
    const float* gamma1 = (const float*)d_in[6];
    const float* beta1  = (const float*)d_in[7];
    const float* W2 = (const float*)d_in[8];
    const float* b2 = (const float*)d_in[9];
    const float* gamma2 = (const float*)d_in[10];
    const float* beta2  = (const float*)d_in[11];
    float* out = (float*)d_out;

    init_kernel<<<1, 256>>>();
    convert_w_kernel<<<(CH * CIN + COUT * CH + 255) / 256, 256>>>(W1, W2);
    transpose_f2_kernel<<<dim3(GPTS / 32, D2 / 32, BATCH), dim3(32, 8)>>>(feature2);
    transpose_f1_kernel<<<dim3(NPTS / 32, D1 / 32, BATCH), dim3(32, 8)>>>(feature1);
    knn_search_kernel<<<dim3(NPTS / 64, BATCH), 256>>>(coord1, coord2);
    knn_gather_kernel<<<NT * 32 / 256, 256>>>();

    gemm_mma_kernel<1><<<NT / 128, 512>>>(b1, nullptr);
    finalize_kernel<1><<<1, CH>>>(gamma1, beta1);
    convert2_kernel<<<NT * 32 / 256, 256>>>();

    gemm_mma_kernel<2><<<NT / 128, 512>>>(b2, out);
    finalize_kernel<2><<<1, COUT>>>(gamma2, beta2);

    apply2_kernel<<<(size_t)BATCH * COUT * NPTS / 4 / 256, 256>>>(out);
}

// round 12
// speedup vs baseline: 1.1008x; 1.1008x over previous
#include <cuda_runtime.h>
#include <cuda_bf16.h>
#include <math_constants.h>
#include <cstdint>

#define BATCH 16
#define NPTS  4096
#define GPTS  1024
#define D1    128
#define D2    256
#define CIN   384
#define CH    256
#define COUT  256
#define NT    (BATCH * NPTS)      /* 65536 flat rows */
#define BN_EPS 1e-5f

#define SROW 40                    /* smem row stride in bf16 (80 B), K-chunk 32 */
#define TILEB (128 * SROW * 2)     /* one tile in bytes (10240) */

// ======================= scratch (device globals) ===========================
__device__ uint4 g_X1hi[(size_t)NT * CIN / 8];   // bf16 [NT][384]
__device__ uint4 g_X1lo[(size_t)NT * CIN / 8];
__device__ uint4 g_X2hi[(size_t)NT * CH / 8];    // bf16 [NT][256]
__device__ uint4 g_X2lo[(size_t)NT * CH / 8];
__device__ float g_Y1t[(size_t)NT * CH];          // fp32 [NT][256]
__device__ float g_f2t[(size_t)BATCH * GPTS * D2];
__device__ float4 g_knnw[NT];                     // (w0,w1,w2,-)
__device__ int4   g_knni[NT];                     // (i0,i1,i2,-)
__device__ uint4 g_W1hi[CH * CIN / 8], g_W1lo[CH * CIN / 8];     // bf16 [256][384]
__device__ uint4 g_W2hi[COUT * CH / 8], g_W2lo[COUT * CH / 8];   // bf16 [256][256]
__device__ float g_sum1[CH],   g_sumsq1[CH];
__device__ float g_sum2[COUT], g_sumsq2[COUT];
__device__ float g_scale1[CH],   g_shift1[CH];
__device__ float g_scale2[COUT], g_shift2[COUT];

// ======================= asm helpers ========================================
__device__ __forceinline__ uint32_t smem_u32(const void* p) {
    uint32_t a;
    asm("{ .reg .u64 t; cvta.to.shared.u64 t, %1; cvt.u32.u64 %0, t; }"
        : "=r"(a) : "l"(p));
    return a;
}

#define CPA16(dst_u32, src_ptr) \
    asm volatile("cp.async.cg.shared.global [%0], [%1], 16;" \
                 :: "r"(dst_u32), "l"(src_ptr) : "memory")
#define CP_COMMIT() asm volatile("cp.async.commit_group;" ::: "memory")
#define CP_WAIT1()  asm volatile("cp.async.wait_group 1;" ::: "memory")
#define CP_WAIT0()  asm volatile("cp.async.wait_group 0;" ::: "memory")

__device__ __forceinline__ void ldsm4(uint32_t addr, uint32_t& r0, uint32_t& r1,
                                      uint32_t& r2, uint32_t& r3) {
    asm volatile("ldmatrix.sync.aligned.m8n8.x4.shared.b16 {%0,%1,%2,%3}, [%4];"
                 : "=r"(r0), "=r"(r1), "=r"(r2), "=r"(r3) : "r"(addr));
}

__device__ __forceinline__ void mma16816(float c[4],
                                         uint32_t a0, uint32_t a1, uint32_t a2, uint32_t a3,
                                         uint32_t b0, uint32_t b1) {
    asm volatile(
        "mma.sync.aligned.m16n8k16.row.col.f32.bf16.bf16.f32 "
        "{%0,%1,%2,%3}, {%4,%5,%6,%7}, {%8,%9}, {%0,%1,%2,%3};"
        : "+f"(c[0]), "+f"(c[1]), "+f"(c[2]), "+f"(c[3])
        : "r"(a0), "r"(a1), "r"(a2), "r"(a3), "r"(b0), "r"(b1));
}

// ======================= small kernels ======================================
__global__ void init_kernel() {
    int t = threadIdx.x;
    g_sum1[t] = 0.f; g_sumsq1[t] = 0.f;
    g_sum2[t] = 0.f; g_sumsq2[t] = 0.f;
}

__device__ __forceinline__ void split1(float v, __nv_bfloat16& h, __nv_bfloat16& l) {
    h = __float2bfloat16(v);
    l = __float2bfloat16(v - __bfloat162float(h));
}

__global__ void convert_w_kernel(const float* __restrict__ W1,
                                 const float* __restrict__ W2) {
    int i = blockIdx.x * blockDim.x + threadIdx.x;
    const int t1 = CH * CIN;
    const int t2 = COUT * CH;
    if (i < t1) {
        __nv_bfloat16 h, l; split1(W1[i], h, l);
        ((__nv_bfloat16*)g_W1hi)[i] = h;
        ((__nv_bfloat16*)g_W1lo)[i] = l;
    } else if (i < t1 + t2) {
        int j = i - t1;
        __nv_bfloat16 h, l; split1(W2[j], h, l);
        ((__nv_bfloat16*)g_W2hi)[j] = h;
        ((__nv_bfloat16*)g_W2lo)[j] = l;
    }
}

// transpose feature2: [B][D2][G] -> [B][G][D2]  (fp32)
__global__ void transpose_f2_kernel(const float* __restrict__ f2) {
    __shared__ float tile[32][33];
    int b  = blockIdx.z;
    int g0 = blockIdx.x * 32;
    int d0 = blockIdx.y * 32;
    const float* src = f2 + (size_t)b * D2 * GPTS;
    #pragma unroll
    for (int r = threadIdx.y; r < 32; r += 8)
        tile[r][threadIdx.x] = src[(size_t)(d0 + r) * GPTS + g0 + threadIdx.x];
    __syncthreads();
    float* dst = g_f2t + (size_t)b * GPTS * D2;
    #pragma unroll
    for (int r = threadIdx.y; r < 32; r += 8)
        dst[(size_t)(g0 + r) * D2 + d0 + threadIdx.x] = tile[threadIdx.x][r];
}

// transpose feature1: [B][D1][N] -> X1 rows [row][0:128] (bf16 hi/lo)
__global__ void transpose_f1_kernel(const float* __restrict__ f1) {
    __shared__ float tile[32][33];
    const int b  = blockIdx.z;
    const int n0 = blockIdx.x * 32;
    const int d0 = blockIdx.y * 32;
    const float* src = f1 + (size_t)b * D1 * NPTS;
    #pragma unroll
    for (int r = threadIdx.y; r < 32; r += 8)
        tile[r][threadIdx.x] = src[(size_t)(d0 + r) * NPTS + n0 + threadIdx.x];
    __syncthreads();
    __nv_bfloat16* hi = (__nv_bfloat16*)g_X1hi;
    __nv_bfloat16* lo = (__nv_bfloat16*)g_X1lo;
    #pragma unroll
    for (int i = threadIdx.y; i < 32; i += 8) {
        const size_t row = (size_t)b * NPTS + n0 + i;
        __nv_bfloat16 h, l;
        split1(tile[threadIdx.x][i], h, l);
        hi[row * CIN + d0 + threadIdx.x] = h;
        lo[row * CIN + d0 + threadIdx.x] = l;
    }
}

__device__ __forceinline__ void split8_store(const float v[8], uint4* hip, uint4* lop) {
    uint32_t h[4], l[4];
    #pragma unroll
    for (int i = 0; i < 4; ++i) {
        __nv_bfloat16 h0, l0, h1, l1;
        split1(v[2 * i], h0, l0);
        split1(v[2 * i + 1], h1, l1);
        h[i] = (uint32_t)__bfloat16_as_ushort(h0) | ((uint32_t)__bfloat16_as_ushort(h1) << 16);
        l[i] = (uint32_t)__bfloat16_as_ushort(l0) | ((uint32_t)__bfloat16_as_ushort(l1) << 16);
    }
    *hip = make_uint4(h[0], h[1], h[2], h[3]);
    *lop = make_uint4(l[0], l[1], l[2], l[3]);
}

// 3-NN search only: 8 lanes x 2 points per group. Block 256 = 32 groups.
__global__ void knn_search_kernel(const float* __restrict__ coord1,
                                  const float* __restrict__ coord2) {
    __shared__ float4 s2[GPTS];
    const int b   = blockIdx.y;
    const int tid = threadIdx.x;
    const int q   = tid & 7;                        // lane within group
    const int nb  = blockIdx.x * 64 + (tid >> 3) * 2;   // first of 2 points

    const float* c2 = coord2 + (size_t)b * 3 * GPTS;
    for (int g = tid; g < GPTS; g += 256) {
        float x = c2[g], y = c2[GPTS + g], z = c2[2 * GPTS + g];
        s2[g] = make_float4(x, y, z, -0.5f * (x * x + y * y + z * z));
    }
    __syncthreads();

    const float* c1 = coord1 + (size_t)b * 3 * NPTS;
    float2 pxv = *(const float2*)(c1 + nb);
    float2 pyv = *(const float2*)(c1 + NPTS + nb);
    float2 pzv = *(const float2*)(c1 + 2 * NPTS + nb);
    const float px[2] = {pxv.x, pxv.y};
    const float py[2] = {pyv.x, pyv.y};
    const float pz[2] = {pzv.x, pzv.y};

    float e0[2], e1[2], e2[2];
    int   i0[2], i1[2], i2[2];
    #pragma unroll
    for (int p = 0; p < 2; ++p) {
        e0[p] = e1[p] = e2[p] = -CUDART_INF_F;
        i0[p] = i1[p] = i2[p] = 0;
    }

    #pragma unroll 4
    for (int it = 0; it < GPTS / 8; ++it) {
        const int g = q + it * 8;
        const float4 c = s2[g];
        #pragma unroll
        for (int p = 0; p < 2; ++p) {
            float e = fmaf(px[p], c.x, fmaf(py[p], c.y, fmaf(pz[p], c.z, c.w)));
            if (e > e2[p]) {
                if (e > e1[p]) {
                    e2[p] = e1[p]; i2[p] = i1[p];
                    if (e > e0[p]) { e1[p] = e0[p]; i1[p] = i0[p]; e0[p] = e; i0[p] = g; }
                    else           { e1[p] = e; i1[p] = g; }
                } else { e2[p] = e; i2[p] = g; }
            }
        }
    }

    #pragma unroll
    for (int off = 1; off <= 4; off <<= 1) {
        #pragma unroll
        for (int p = 0; p < 2; ++p) {
            float f0 = __shfl_xor_sync(0xffffffffu, e0[p], off);
            float f1 = __shfl_xor_sync(0xffffffffu, e1[p], off);
            float f2 = __shfl_xor_sync(0xffffffffu, e2[p], off);
            int   j0 = __shfl_xor_sync(0xffffffffu, i0[p], off);
            int   j1 = __shfl_xor_sync(0xffffffffu, i1[p], off);
            int   j2 = __shfl_xor_sync(0xffffffffu, i2[p], off);
            float m0, m1, m2; int k0, k1, k2;
            if (e0[p] >= f0) {
                m0 = e0[p]; k0 = i0[p];
                if (e1[p] >= f0) {
                    m1 = e1[p]; k1 = i1[p];
                    if (e2[p] >= f0) { m2 = e2[p]; k2 = i2[p]; } else { m2 = f0; k2 = j0; }
                } else {
                    m1 = f0; k1 = j0;
                    if (e1[p] >= f1) { m2 = e1[p]; k2 = i1[p]; } else { m2 = f1; k2 = j1; }
                }
            } else {
                m0 = f0; k0 = j0;
                if (f1 >= e0[p]) {
                    m1 = f1; k1 = j1;
                    if (f2 >= e0[p]) { m2 = f2; k2 = j2; } else { m2 = e0[p]; k2 = i0[p]; }
                } else {
                    m1 = e0[p]; k1 = i0[p];
                    if (f1 >= e1[p]) { m2 = f1; k2 = j1; } else { m2 = e1[p]; k2 = i1[p]; }
                }
            }
            e0[p] = m0; i0[p] = k0; e1[p] = m1; i1[p] = k1; e2[p] = m2; i2[p] = k2;
        }
    }

    if (q == 0) {
        #pragma unroll
        for (int p = 0; p < 2; ++p) {
            const float qn = px[p] * px[p] + py[p] * py[p] + pz[p] * pz[p];
            const float d0 = qn - 2.0f * e0[p];
            const float d1 = qn - 2.0f * e1[p];
            const float d2 = qn - 2.0f * e2[p];
            const float r0w = 1.0f / (d0 + 1e-8f);
            const float r1w = 1.0f / (d1 + 1e-8f);
            const float r2w = 1.0f / (d2 + 1e-8f);
            const float rs = 1.0f / (r0w + r1w + r2w);
            const size_t row = (size_t)b * NPTS + nb + p;
            g_knnw[row] = make_float4(r0w * rs, r1w * rs, r2w * rs, 0.f);
            g_knni[row] = make_int4(i0[p], i1[p], i2[p], 0);
        }
    }
}

// gather + interp: one warp per point; lane c handles interp chunk c (0..31).
__global__ void knn_gather_kernel() {
    const int gid = blockIdx.x * 256 + threadIdx.x;
    const size_t r = (size_t)(gid >> 5);      // point row
    const int c = gid & 31;                   // d8 chunk within D2
    const int b = (int)(r >> 12);

    const float4 w = g_knnw[r];
    const int4  ii = g_knni[r];
    const float* F = g_f2t + (size_t)b * GPTS * D2;
    const float4* p0 = (const float4*)(F + (size_t)ii.x * D2);
    const float4* p1 = (const float4*)(F + (size_t)ii.y * D2);
    const float4* p2 = (const float4*)(F + (size_t)ii.z * D2);

    float4 a0 = p0[2 * c], a1 = p0[2 * c + 1];
    float4 b0 = p1[2 * c], b1 = p1[2 * c + 1];
    float4 g0 = p2[2 * c], g1 = p2[2 * c + 1];
    float v[8];
    v[0] = w.x * a0.x + w.y * b0.x + w.z * g0.x;
    v[1] = w.x * a0.y + w.y * b0.y + w.z * g0.y;
    v[2] = w.x * a0.z + w.y * b0.z + w.z * g0.z;
    v[3] = w.x * a0.w + w.y * b0.w + w.z * g0.w;
    v[4] = w.x * a1.x + w.y * b1.x + w.z * g1.x;
    v[5] = w.x * a1.y + w.y * b1.y + w.z * g1.y;
    v[6] = w.x * a1.z + w.y * b1.z + w.z * g1.z;
    v[7] = w.x * a1.w + w.y * b1.w + w.z * g1.w;
    split8_store(v, g_X1hi + r * (CIN / 8) + D1 / 8 + c,
                    g_X1lo + r * (CIN / 8) + D1 / 8 + c);
}

// ======================= HMMA GEMM (fused split-phases, ldmatrix) ===========
// C[m][n] = Whi*Xhi + Whi*Xlo + Wlo*Xhi, all three per K32 chunk so every
// tile is loaded exactly once. CTA tile 128(M)x128(N), 2-stage cp.async.
// 8 warps = 2(M)x4(N). Fragments via ldmatrix.x4 (padded SROW=40 rows are
// conflict-free: stride 20 words covers all 32 banks across 8 rows).
// LAYER1 epilogue -> g_Y1t[n][m]; LAYER2 -> out[b][m][n].
template <int LAYER>
__global__ void __launch_bounds__(256, 2)
gemm_mma_kernel(const float* __restrict__ bias, float* __restrict__ outp) {
    constexpr int K0 = (LAYER == 1) ? CIN : CH;
    constexpr int NC = K0 / 32;

    const __nv_bfloat16* Whi = (LAYER == 1) ? (const __nv_bfloat16*)g_W1hi
                                            : (const __nv_bfloat16*)g_W2hi;
    const __nv_bfloat16* Wlo = (LAYER == 1) ? (const __nv_bfloat16*)g_W1lo
                                            : (const __nv_bfloat16*)g_W2lo;
    const __nv_bfloat16* Xhi = (LAYER == 1) ? (const __nv_bfloat16*)g_X1hi
                                            : (const __nv_bfloat16*)g_X2hi;
    const __nv_bfloat16* Xlo = (LAYER == 1) ? (const __nv_bfloat16*)g_X1lo
                                            : (const __nv_bfloat16*)g_X2lo;
    float* gsum  = (LAYER == 1) ? g_sum1 : g_sum2;
    float* gsq   = (LAYER == 1) ? g_sumsq1 : g_sumsq2;

    __shared__ __align__(16) __nv_bfloat16 sAhi[2][128 * SROW];
    __shared__ __align__(16) __nv_bfloat16 sAlo[2][128 * SROW];
    __shared__ __align__(16) __nv_bfloat16 sBhi[2][128 * SROW];
    __shared__ __align__(16) __nv_bfloat16 sBlo[2][128 * SROW];

    const int tid  = threadIdx.x;
    const int wid  = tid >> 5, lane = tid & 31;
    const int tg   = lane >> 2;            // groupID (0..7)
    const int tig  = lane & 3;             // threadID_in_group (0..3)
    const size_t r0 = (size_t)blockIdx.x * 128;   // X row block
    const int m0 = blockIdx.y * 128;              // W row block
    const int wm = (wid & 1) * 64;
    const int wn = (wid >> 1) * 32;

    const uint32_t aAhi = smem_u32(sAhi);
    const uint32_t aAlo = smem_u32(sAlo);
    const uint32_t aBhi = smem_u32(sBhi);
    const uint32_t aBlo = smem_u32(sBlo);
    const int ldr  = tid >> 2;             // load row (0..63), +64 second half
    const int ldch = tid & 3;              // 16B chunk in row (32 cols = 4)
    const uint32_t ldoff = (uint32_t)(ldr * SROW * 2 + ldch * 16);

    // ldmatrix per-lane address components: row = lane&15, col-half = lane>>4
    const uint32_t lmoff = (uint32_t)((lane & 15) * SROW * 2 + (lane >> 4) * 16);

    float acc[4][4][4];
    #pragma unroll
    for (int i = 0; i < 4; ++i)
        #pragma unroll
        for (int j = 0; j < 4; ++j)
            #pragma unroll
            for (int k = 0; k < 4; ++k) acc[i][j][k] = 0.f;

    auto issue = [&](int c, int st) {
        const int kk = c * 32;
        const uint32_t so = (uint32_t)st * TILEB + ldoff;
        #pragma unroll
        for (int i = 0; i < 2; ++i) {
            const int r = ldr + i * 64;
            const uint32_t d = so + (uint32_t)(i * 64 * SROW * 2);
            const size_t ga = (size_t)(m0 + r) * K0 + kk + ldch * 8;
            const size_t gb = (r0 + r) * K0 + kk + ldch * 8;
            CPA16(aAhi + d, Whi + ga);
            CPA16(aAlo + d, Wlo + ga);
            CPA16(aBhi + d, Xhi + gb);
            CPA16(aBlo + d, Xlo + gb);
        }
        CP_COMMIT();
    };

    issue(0, 0);
    for (int c = 0; c < NC; ++c) {
        const int st = c & 1;
        if (c + 1 < NC) { issue(c + 1, st ^ 1); CP_WAIT1(); }
        else            { CP_WAIT0(); }
        __syncthreads();

        const uint32_t uAhi = aAhi + (uint32_t)st * TILEB + lmoff;
        const uint32_t uAlo = aAlo + (uint32_t)st * TILEB + lmoff;
        const uint32_t uBhi = aBhi + (uint32_t)st * TILEB + lmoff;
        const uint32_t uBlo = aBlo + (uint32_t)st * TILEB + lmoff;
        #pragma unroll
        for (int ks = 0; ks < 2; ++ks) {      // k16 steps within 32-chunk
            const uint32_t kboff = (uint32_t)(ks * 32);   // 16 bf16 = 32 bytes
            // B-hi fragments: two ldmatrix.x4 (nj = 0,1)
            uint32_t bh[4][2];
            #pragma unroll
            for (int nj = 0; nj < 2; ++nj) {
                uint32_t t0, t1, t2, t3;
                ldsm4(uBhi + (uint32_t)((wn + nj * 16) * SROW * 2) + kboff,
                      t0, t1, t2, t3);
                bh[nj * 2][0]     = t0; bh[nj * 2][1]     = t2;
                bh[nj * 2 + 1][0] = t1; bh[nj * 2 + 1][1] = t3;
            }
            // A-hi fragments: four ldmatrix.x4 (mi = 0..3)
            uint32_t ah[4][4];
            #pragma unroll
            for (int mi = 0; mi < 4; ++mi)
                ldsm4(uAhi + (uint32_t)((wm + mi * 16) * SROW * 2) + kboff,
                      ah[mi][0], ah[mi][1], ah[mi][2], ah[mi][3]);

            // phase hh: Whi * Xhi
            #pragma unroll
            for (int mi = 0; mi < 4; ++mi)
                #pragma unroll
                for (int ni = 0; ni < 4; ++ni)
                    mma16816(acc[mi][ni], ah[mi][0], ah[mi][1], ah[mi][2], ah[mi][3],
                             bh[ni][0], bh[ni][1]);
            // phase hl: Whi * Xlo (reuse ah)
            #pragma unroll
            for (int nj = 0; nj < 2; ++nj) {
                uint32_t t0, t1, t2, t3;
                ldsm4(uBlo + (uint32_t)((wn + nj * 16) * SROW * 2) + kboff,
                      t0, t1, t2, t3);
                uint32_t bl[2][2];
                bl[0][0] = t0; bl[0][1] = t2;
                bl[1][0] = t1; bl[1][1] = t3;
                #pragma unroll
                for (int jj = 0; jj < 2; ++jj) {
                    const int ni = nj * 2 + jj;
                    #pragma unroll
                    for (int mi = 0; mi < 4; ++mi)
                        mma16816(acc[mi][ni], ah[mi][0], ah[mi][1], ah[mi][2], ah[mi][3],
                                 bl[jj][0], bl[jj][1]);
                }
            }
            // phase lh: Wlo * Xhi (reuse bh)
            #pragma unroll
            for (int mi = 0; mi < 4; ++mi) {
                uint32_t al0, al1, al2, al3;
                ldsm4(uAlo + (uint32_t)((wm + mi * 16) * SROW * 2) + kboff,
                      al0, al1, al2, al3);
                #pragma unroll
                for (int ni = 0; ni < 4; ++ni)
                    mma16816(acc[mi][ni], al0, al1, al2, al3, bh[ni][0], bh[ni][1]);
            }
        }
        __syncthreads();
    }

    // epilogue: store + fused BN stats
    const int bb = (int)(r0 >> 12);            // batch (LAYER2)
    const int n0 = (int)(r0 & (NPTS - 1));     // n offset within batch
    #pragma unroll
    for (int mi = 0; mi < 4; ++mi) {
        const int mg0 = m0 + wm + mi * 16 + tg;
        const int mg1 = mg0 + 8;
        const float bv0 = bias[mg0];
        const float bv1 = bias[mg1];
        float s0 = 0.f, q0 = 0.f, s1 = 0.f, q1 = 0.f;
        #pragma unroll
        for (int ni = 0; ni < 4; ++ni) {
            const float v00 = acc[mi][ni][0] + bv0;
            const float v01 = acc[mi][ni][1] + bv0;
            const float v10 = acc[mi][ni][2] + bv1;
            const float v11 = acc[mi][ni][3] + bv1;
            if (LAYER == 1) {
                const size_t n = r0 + wn + ni * 8 + 2 * tig;
                g_Y1t[n * 256 + mg0]       = v00;
                g_Y1t[(n + 1) * 256 + mg0] = v01;
                g_Y1t[n * 256 + mg1]       = v10;
                g_Y1t[(n + 1) * 256 + mg1] = v11;
            } else {
                const int nloc = n0 + wn + ni * 8 + 2 * tig;
                *(float2*)(outp + ((size_t)bb * 256 + mg0) * NPTS + nloc) =
                    make_float2(v00, v01);
                *(float2*)(outp + ((size_t)bb * 256 + mg1) * NPTS + nloc) =
                    make_float2(v10, v11);
            }
            s0 += v00 + v01; q0 += v00 * v00 + v01 * v01;
            s1 += v10 + v11; q1 += v10 * v10 + v11 * v11;
        }
        #pragma unroll
        for (int off = 1; off <= 2; off <<= 1) {
            s0 += __shfl_xor_sync(0xffffffffu, s0, off);
            q0 += __shfl_xor_sync(0xffffffffu, q0, off);
            s1 += __shfl_xor_sync(0xffffffffu, s1, off);
            q1 += __shfl_xor_sync(0xffffffffu, q1, off);
        }
        if (tig == 0) {
            atomicAdd(&gsum[mg0], s0); atomicAdd(&gsq[mg0], q0);
            atomicAdd(&gsum[mg1], s1); atomicAdd(&gsq[mg1], q1);
        }
    }
}

// ======================= finalize / fold ====================================
template <int LAYER>
__global__ void finalize_kernel(const float* __restrict__ gamma,
                                const float* __restrict__ beta) {
    const float* gsum = (LAYER == 1) ? g_sum1 : g_sum2;
    const float* gsq  = (LAYER == 1) ? g_sumsq1 : g_sumsq2;
    float* scale      = (LAYER == 1) ? g_scale1 : g_scale2;
    float* shift      = (LAYER == 1) ? g_shift1 : g_shift2;
    const int c = threadIdx.x;
    const float inv = 1.0f / (float)((size_t)NT);
    float m  = gsum[c] * inv;
    float v  = fmaxf(gsq[c] * inv - m * m, 0.f);
    float sc = gamma[c] * rsqrtf(v + BN_EPS);
    scale[c] = sc;
    shift[c] = beta[c] - m * sc;
}

// BN1 + ReLU + bf16 split: Y1t [row][256] -> X2hi/X2lo [row][256]
__global__ void convert2_kernel() {
    const int gid = blockIdx.x * 256 + threadIdx.x;       // one per 8 channels
    const size_t r = (size_t)(gid >> 5);
    const int c0 = (gid & 31) * 8;
    const float* p = g_Y1t + r * 256 + c0;
    float4 a = *(const float4*)(p);
    float4 b = *(const float4*)(p + 4);
    float4 s0 = *(const float4*)(g_scale1 + c0);
    float4 s1 = *(const float4*)(g_scale1 + c0 + 4);
    float4 t0 = *(const float4*)(g_shift1 + c0);
    float4 t1 = *(const float4*)(g_shift1 + c0 + 4);
    float v[8];
    v[0] = fmaxf(fmaf(a.x, s0.x, t0.x), 0.f);
    v[1] = fmaxf(fmaf(a.y, s0.y, t0.y), 0.f);
    v[2] = fmaxf(fmaf(a.z, s0.z, t0.z), 0.f);
    v[3] = fmaxf(fmaf(a.w, s0.w, t0.w), 0.f);
    v[4] = fmaxf(fmaf(b.x, s1.x, t1.x), 0.f);
    v[5] = fmaxf(fmaf(b.y, s1.y, t1.y), 0.f);
    v[6] = fmaxf(fmaf(b.z, s1.z, t1.z), 0.f);
    v[7] = fmaxf(fmaf(b.w, s1.w, t1.w), 0.f);
    split8_store(v, g_X2hi + (r * 256 + c0) / 8, g_X2lo + (r * 256 + c0) / 8);
}

// final: BN2 + ReLU in place on out [b][m][n]
__global__ void apply2_kernel(float* __restrict__ out) {
    const int i4 = blockIdx.x * 256 + threadIdx.x;   // float4 index
    const int c  = (i4 >> 10) & 255;                 // NPTS/4 = 1024 f4 per row
    const float s = g_scale2[c], t = g_shift2[c];
    float4 v = ((float4*)out)[i4];
    v.x = fmaxf(fmaf(v.x, s, t), 0.f);
    v.y = fmaxf(fmaf(v.y, s, t), 0.f);
    v.z = fmaxf(fmaf(v.z, s, t), 0.f);
    v.w = fmaxf(fmaf(v.w, s, t), 0.f);
    ((float4*)out)[i4] = v;
}

// ======================= launch =============================================
extern "C" void kernel_launch(void* const* d_in, const int* in_sizes, int n_in,
                              void* d_out, int out_size) {
    const float* feature1 = (const float*)d_in[0];
    const float* coord1   = (const float*)d_in[1];
    const float* feature2 = (const float*)d_in[2];
    const float* coord2   = (const float*)d_in[3];
    const float* W1 = (const float*)d_in[4];
    const float* b1 = (const float*)d_in[5];
    const float* gamma1 = (const float*)d_in[6];
    const float* beta1  = (const float*)d_in[7];
    const float* W2 = (const float*)d_in[8];
    const float* b2 = (const float*)d_in[9];
    const float* gamma2 = (const float*)d_in[10];
    const float* beta2  = (const float*)d_in[11];
    float* out = (float*)d_out;

    init_kernel<<<1, 256>>>();
    convert_w_kernel<<<(CH * CIN + COUT * CH + 255) / 256, 256>>>(W1, W2);
    transpose_f2_kernel<<<dim3(GPTS / 32, D2 / 32, BATCH), dim3(32, 8)>>>(feature2);
    transpose_f1_kernel<<<dim3(NPTS / 32, D1 / 32, BATCH), dim3(32, 8)>>>(feature1);
    knn_search_kernel<<<dim3(NPTS / 64, BATCH), 256>>>(coord1, coord2);
    knn_gather_kernel<<<NT * 32 / 256, 256>>>();

    gemm_mma_kernel<1><<<dim3(NT / 128, 2), 256>>>(b1, nullptr);
    finalize_kernel<1><<<1, CH>>>(gamma1, beta1);
    convert2_kernel<<<NT * 32 / 256, 256>>>();

    gemm_mma_kernel<2><<<dim3(NT / 128, 2), 256>>>(b2, out);
    finalize_kernel<2><<<1, COUT>>>(gamma2, beta2);

    apply2_kernel<<<(size_t)BATCH * COUT * NPTS / 4 / 256, 256>>>(out);
}

// round 13
// speedup vs baseline: 1.1388x; 1.0345x over previous
#include <cuda_runtime.h>
#include <cuda_bf16.h>
#include <math_constants.h>
#include <cstdint>

#define BATCH 16
#define NPTS  4096
#define GPTS  1024
#define D1    128
#define D2    256
#define CIN   384
#define CH    256
#define COUT  256
#define NT    (BATCH * NPTS)      /* 65536 flat rows */
#define BN_EPS 1e-5f

#define SROW 40                    /* smem row stride in bf16 (80 B), K-chunk 32 */
#define TILEB (128 * SROW * 2)     /* one tile in bytes (10240) */

// ======================= scratch (device globals) ===========================
__device__ uint4 g_X1hi[(size_t)NT * CIN / 8];   // bf16 [NT][384]
__device__ uint4 g_X1lo[(size_t)NT * CIN / 8];
__device__ uint4 g_X2hi[(size_t)NT * CH / 8];    // bf16 [NT][256]
__device__ uint4 g_X2lo[(size_t)NT * CH / 8];
__device__ float g_Y1t[(size_t)NT * CH];          // fp32 [NT][256]
__device__ float g_f2t[(size_t)BATCH * GPTS * D2];
__device__ float4 g_knnw[NT];                     // (w0,w1,w2,-)
__device__ int4   g_knni[NT];                     // (i0,i1,i2,-)
__device__ uint4 g_W1hi[CH * CIN / 8], g_W1lo[CH * CIN / 8];     // bf16 [256][384]
__device__ uint4 g_W2hi[COUT * CH / 8], g_W2lo[COUT * CH / 8];   // bf16 [256][256]
__device__ float g_sum1[CH],   g_sumsq1[CH];
__device__ float g_sum2[COUT], g_sumsq2[COUT];
__device__ float g_scale1[CH],   g_shift1[CH];
__device__ float g_scale2[COUT], g_shift2[COUT];

// ======================= asm helpers ========================================
__device__ __forceinline__ uint32_t smem_u32(const void* p) {
    uint32_t a;
    asm("{ .reg .u64 t; cvta.to.shared.u64 t, %1; cvt.u32.u64 %0, t; }"
        : "=r"(a) : "l"(p));
    return a;
}

#define CPA16(dst_u32, src_ptr) \
    asm volatile("cp.async.cg.shared.global [%0], [%1], 16;" \
                 :: "r"(dst_u32), "l"(src_ptr) : "memory")
#define CP_COMMIT() asm volatile("cp.async.commit_group;" ::: "memory")
#define CP_WAIT1()  asm volatile("cp.async.wait_group 1;" ::: "memory")
#define CP_WAIT0()  asm volatile("cp.async.wait_group 0;" ::: "memory")

__device__ __forceinline__ void mma16816(float c[4],
                                         uint32_t a0, uint32_t a1, uint32_t a2, uint32_t a3,
                                         uint32_t b0, uint32_t b1) {
    asm volatile(
        "mma.sync.aligned.m16n8k16.row.col.f32.bf16.bf16.f32 "
        "{%0,%1,%2,%3}, {%4,%5,%6,%7}, {%8,%9}, {%0,%1,%2,%3};"
        : "+f"(c[0]), "+f"(c[1]), "+f"(c[2]), "+f"(c[3])
        : "r"(a0), "r"(a1), "r"(a2), "r"(a3), "r"(b0), "r"(b1));
}

// ======================= small kernels ======================================
__global__ void init_kernel() {
    int t = threadIdx.x;
    g_sum1[t] = 0.f; g_sumsq1[t] = 0.f;
    g_sum2[t] = 0.f; g_sumsq2[t] = 0.f;
}

__device__ __forceinline__ void split1(float v, __nv_bfloat16& h, __nv_bfloat16& l) {
    h = __float2bfloat16(v);
    l = __float2bfloat16(v - __bfloat162float(h));
}

__global__ void convert_w_kernel(const float* __restrict__ W1,
                                 const float* __restrict__ W2) {
    int i = blockIdx.x * blockDim.x + threadIdx.x;
    const int t1 = CH * CIN;
    const int t2 = COUT * CH;
    if (i < t1) {
        __nv_bfloat16 h, l; split1(W1[i], h, l);
        ((__nv_bfloat16*)g_W1hi)[i] = h;
        ((__nv_bfloat16*)g_W1lo)[i] = l;
    } else if (i < t1 + t2) {
        int j = i - t1;
        __nv_bfloat16 h, l; split1(W2[j], h, l);
        ((__nv_bfloat16*)g_W2hi)[j] = h;
        ((__nv_bfloat16*)g_W2lo)[j] = l;
    }
}

// transpose feature2: [B][D2][G] -> [B][G][D2]  (fp32)
__global__ void transpose_f2_kernel(const float* __restrict__ f2) {
    __shared__ float tile[32][33];
    int b  = blockIdx.z;
    int g0 = blockIdx.x * 32;
    int d0 = blockIdx.y * 32;
    const float* src = f2 + (size_t)b * D2 * GPTS;
    #pragma unroll
    for (int r = threadIdx.y; r < 32; r += 8)
        tile[r][threadIdx.x] = src[(size_t)(d0 + r) * GPTS + g0 + threadIdx.x];
    __syncthreads();
    float* dst = g_f2t + (size_t)b * GPTS * D2;
    #pragma unroll
    for (int r = threadIdx.y; r < 32; r += 8)
        dst[(size_t)(g0 + r) * D2 + d0 + threadIdx.x] = tile[threadIdx.x][r];
}

// transpose feature1: [B][D1][N] -> X1 rows [row][0:128] (bf16 hi/lo)
__global__ void transpose_f1_kernel(const float* __restrict__ f1) {
    __shared__ float tile[32][33];
    const int b  = blockIdx.z;
    const int n0 = blockIdx.x * 32;
    const int d0 = blockIdx.y * 32;
    const float* src = f1 + (size_t)b * D1 * NPTS;
    #pragma unroll
    for (int r = threadIdx.y; r < 32; r += 8)
        tile[r][threadIdx.x] = src[(size_t)(d0 + r) * NPTS + n0 + threadIdx.x];
    __syncthreads();
    __nv_bfloat16* hi = (__nv_bfloat16*)g_X1hi;
    __nv_bfloat16* lo = (__nv_bfloat16*)g_X1lo;
    #pragma unroll
    for (int i = threadIdx.y; i < 32; i += 8) {
        const size_t row = (size_t)b * NPTS + n0 + i;
        __nv_bfloat16 h, l;
        split1(tile[threadIdx.x][i], h, l);
        hi[row * CIN + d0 + threadIdx.x] = h;
        lo[row * CIN + d0 + threadIdx.x] = l;
    }
}

__device__ __forceinline__ void split8_store(const float v[8], uint4* hip, uint4* lop) {
    uint32_t h[4], l[4];
    #pragma unroll
    for (int i = 0; i < 4; ++i) {
        __nv_bfloat16 h0, l0, h1, l1;
        split1(v[2 * i], h0, l0);
        split1(v[2 * i + 1], h1, l1);
        h[i] = (uint32_t)__bfloat16_as_ushort(h0) | ((uint32_t)__bfloat16_as_ushort(h1) << 16);
        l[i] = (uint32_t)__bfloat16_as_ushort(l0) | ((uint32_t)__bfloat16_as_ushort(l1) << 16);
    }
    *hip = make_uint4(h[0], h[1], h[2], h[3]);
    *lop = make_uint4(l[0], l[1], l[2], l[3]);
}

// 3-NN search only: 8 lanes x 2 points per group. Block 256 = 32 groups.
__global__ void knn_search_kernel(const float* __restrict__ coord1,
                                  const float* __restrict__ coord2) {
    __shared__ float4 s2[GPTS];
    const int b   = blockIdx.y;
    const int tid = threadIdx.x;
    const int q   = tid & 7;                        // lane within group
    const int nb  = blockIdx.x * 64 + (tid >> 3) * 2;   // first of 2 points

    const float* c2 = coord2 + (size_t)b * 3 * GPTS;
    for (int g = tid; g < GPTS; g += 256) {
        float x = c2[g], y = c2[GPTS + g], z = c2[2 * GPTS + g];
        s2[g] = make_float4(x, y, z, -0.5f * (x * x + y * y + z * z));
    }
    __syncthreads();

    const float* c1 = coord1 + (size_t)b * 3 * NPTS;
    float2 pxv = *(const float2*)(c1 + nb);
    float2 pyv = *(const float2*)(c1 + NPTS + nb);
    float2 pzv = *(const float2*)(c1 + 2 * NPTS + nb);
    const float px[2] = {pxv.x, pxv.y};
    const float py[2] = {pyv.x, pyv.y};
    const float pz[2] = {pzv.x, pzv.y};

    float e0[2], e1[2], e2[2];
    int   i0[2], i1[2], i2[2];
    #pragma unroll
    for (int p = 0; p < 2; ++p) {
        e0[p] = e1[p] = e2[p] = -CUDART_INF_F;
        i0[p] = i1[p] = i2[p] = 0;
    }

    #pragma unroll 4
    for (int it = 0; it < GPTS / 8; ++it) {
        const int g = q + it * 8;
        const float4 c = s2[g];
        #pragma unroll
        for (int p = 0; p < 2; ++p) {
            float e = fmaf(px[p], c.x, fmaf(py[p], c.y, fmaf(pz[p], c.z, c.w)));
            if (e > e2[p]) {
                if (e > e1[p]) {
                    e2[p] = e1[p]; i2[p] = i1[p];
                    if (e > e0[p]) { e1[p] = e0[p]; i1[p] = i0[p]; e0[p] = e; i0[p] = g; }
                    else           { e1[p] = e; i1[p] = g; }
                } else { e2[p] = e; i2[p] = g; }
            }
        }
    }

    #pragma unroll
    for (int off = 1; off <= 4; off <<= 1) {
        #pragma unroll
        for (int p = 0; p < 2; ++p) {
            float f0 = __shfl_xor_sync(0xffffffffu, e0[p], off);
            float f1 = __shfl_xor_sync(0xffffffffu, e1[p], off);
            float f2 = __shfl_xor_sync(0xffffffffu, e2[p], off);
            int   j0 = __shfl_xor_sync(0xffffffffu, i0[p], off);
            int   j1 = __shfl_xor_sync(0xffffffffu, i1[p], off);
            int   j2 = __shfl_xor_sync(0xffffffffu, i2[p], off);
            float m0, m1, m2; int k0, k1, k2;
            if (e0[p] >= f0) {
                m0 = e0[p]; k0 = i0[p];
                if (e1[p] >= f0) {
                    m1 = e1[p]; k1 = i1[p];
                    if (e2[p] >= f0) { m2 = e2[p]; k2 = i2[p]; } else { m2 = f0; k2 = j0; }
                } else {
                    m1 = f0; k1 = j0;
                    if (e1[p] >= f1) { m2 = e1[p]; k2 = i1[p]; } else { m2 = f1; k2 = j1; }
                }
            } else {
                m0 = f0; k0 = j0;
                if (f1 >= e0[p]) {
                    m1 = f1; k1 = j1;
                    if (f2 >= e0[p]) { m2 = f2; k2 = j2; } else { m2 = e0[p]; k2 = i0[p]; }
                } else {
                    m1 = e0[p]; k1 = i0[p];
                    if (f1 >= e1[p]) { m2 = f1; k2 = j1; } else { m2 = e1[p]; k2 = i1[p]; }
                }
            }
            e0[p] = m0; i0[p] = k0; e1[p] = m1; i1[p] = k1; e2[p] = m2; i2[p] = k2;
        }
    }

    if (q == 0) {
        #pragma unroll
        for (int p = 0; p < 2; ++p) {
            const float qn = px[p] * px[p] + py[p] * py[p] + pz[p] * pz[p];
            const float d0 = qn - 2.0f * e0[p];
            const float d1 = qn - 2.0f * e1[p];
            const float d2 = qn - 2.0f * e2[p];
            const float r0w = 1.0f / (d0 + 1e-8f);
            const float r1w = 1.0f / (d1 + 1e-8f);
            const float r2w = 1.0f / (d2 + 1e-8f);
            const float rs = 1.0f / (r0w + r1w + r2w);
            const size_t row = (size_t)b * NPTS + nb + p;
            g_knnw[row] = make_float4(r0w * rs, r1w * rs, r2w * rs, 0.f);
            g_knni[row] = make_int4(i0[p], i1[p], i2[p], 0);
        }
    }
}

// gather + interp: one warp per point; lane c handles interp chunk c (0..31).
__global__ void knn_gather_kernel() {
    const int gid = blockIdx.x * 256 + threadIdx.x;
    const size_t r = (size_t)(gid >> 5);      // point row
    const int c = gid & 31;                   // d8 chunk within D2
    const int b = (int)(r >> 12);

    const float4 w = g_knnw[r];
    const int4  ii = g_knni[r];
    const float* F = g_f2t + (size_t)b * GPTS * D2;
    const float4* p0 = (const float4*)(F + (size_t)ii.x * D2);
    const float4* p1 = (const float4*)(F + (size_t)ii.y * D2);
    const float4* p2 = (const float4*)(F + (size_t)ii.z * D2);

    float4 a0 = p0[2 * c], a1 = p0[2 * c + 1];
    float4 b0 = p1[2 * c], b1 = p1[2 * c + 1];
    float4 g0 = p2[2 * c], g1 = p2[2 * c + 1];
    float v[8];
    v[0] = w.x * a0.x + w.y * b0.x + w.z * g0.x;
    v[1] = w.x * a0.y + w.y * b0.y + w.z * g0.y;
    v[2] = w.x * a0.z + w.y * b0.z + w.z * g0.z;
    v[3] = w.x * a0.w + w.y * b0.w + w.z * g0.w;
    v[4] = w.x * a1.x + w.y * b1.x + w.z * g1.x;
    v[5] = w.x * a1.y + w.y * b1.y + w.z * g1.y;
    v[6] = w.x * a1.z + w.y * b1.z + w.z * g1.z;
    v[7] = w.x * a1.w + w.y * b1.w + w.z * g1.w;
    split8_store(v, g_X1hi + r * (CIN / 8) + D1 / 8 + c,
                    g_X1lo + r * (CIN / 8) + D1 / 8 + c);
}

// ======================= HMMA GEMM (fused split-phases) =====================
// C[m][n] = Whi*Xhi + Whi*Xlo + Wlo*Xhi, all three per K32 chunk so every
// tile is loaded exactly once. CTA tile 128(M)x128(N), 2-stage cp.async.
// 8 warps = 2(M)x4(N). Grid (2, NT/128): the two CTAs sharing X rows are
// launch-adjacent -> co-resident -> the second one's X loads hit L2.
// LAYER1 epilogue -> g_Y1t[n][m]; LAYER2 -> out[b][m][n].
template <int LAYER>
__global__ void __launch_bounds__(256, 2)
gemm_mma_kernel(const float* __restrict__ bias, float* __restrict__ outp) {
    constexpr int K0 = (LAYER == 1) ? CIN : CH;
    constexpr int NC = K0 / 32;

    const __nv_bfloat16* Whi = (LAYER == 1) ? (const __nv_bfloat16*)g_W1hi
                                            : (const __nv_bfloat16*)g_W2hi;
    const __nv_bfloat16* Wlo = (LAYER == 1) ? (const __nv_bfloat16*)g_W1lo
                                            : (const __nv_bfloat16*)g_W2lo;
    const __nv_bfloat16* Xhi = (LAYER == 1) ? (const __nv_bfloat16*)g_X1hi
                                            : (const __nv_bfloat16*)g_X2hi;
    const __nv_bfloat16* Xlo = (LAYER == 1) ? (const __nv_bfloat16*)g_X1lo
                                            : (const __nv_bfloat16*)g_X2lo;
    float* gsum  = (LAYER == 1) ? g_sum1 : g_sum2;
    float* gsq   = (LAYER == 1) ? g_sumsq1 : g_sumsq2;

    __shared__ __align__(16) __nv_bfloat16 sAhi[2][128 * SROW];
    __shared__ __align__(16) __nv_bfloat16 sAlo[2][128 * SROW];
    __shared__ __align__(16) __nv_bfloat16 sBhi[2][128 * SROW];
    __shared__ __align__(16) __nv_bfloat16 sBlo[2][128 * SROW];

    const int tid  = threadIdx.x;
    const int wid  = tid >> 5, lane = tid & 31;
    const int tg   = lane >> 2;            // groupID (0..7)
    const int tig  = lane & 3;             // threadID_in_group (0..3)
    const size_t r0 = (size_t)blockIdx.y * 128;   // X row block
    const int m0 = blockIdx.x * 128;              // W row block
    const int wm = (wid & 1) * 64;
    const int wn = (wid >> 1) * 32;

    const uint32_t aAhi = smem_u32(sAhi);
    const uint32_t aAlo = smem_u32(sAlo);
    const uint32_t aBhi = smem_u32(sBhi);
    const uint32_t aBlo = smem_u32(sBlo);
    const int ldr  = tid >> 2;             // load row (0..63), +64 second half
    const int ldch = tid & 3;              // 16B chunk in row (32 cols = 4)
    const uint32_t ldoff = (uint32_t)(ldr * SROW * 2 + ldch * 16);

    float acc[4][4][4];
    #pragma unroll
    for (int i = 0; i < 4; ++i)
        #pragma unroll
        for (int j = 0; j < 4; ++j)
            #pragma unroll
            for (int k = 0; k < 4; ++k) acc[i][j][k] = 0.f;

    auto issue = [&](int c, int st) {
        const int kk = c * 32;
        const uint32_t so = (uint32_t)st * TILEB + ldoff;
        #pragma unroll
        for (int i = 0; i < 2; ++i) {
            const int r = ldr + i * 64;
            const uint32_t d = so + (uint32_t)(i * 64 * SROW * 2);
            const size_t ga = (size_t)(m0 + r) * K0 + kk + ldch * 8;
            const size_t gb = (r0 + r) * K0 + kk + ldch * 8;
            CPA16(aAhi + d, Whi + ga);
            CPA16(aAlo + d, Wlo + ga);
            CPA16(aBhi + d, Xhi + gb);
            CPA16(aBlo + d, Xlo + gb);
        }
        CP_COMMIT();
    };

    issue(0, 0);
    for (int c = 0; c < NC; ++c) {
        const int st = c & 1;
        if (c + 1 < NC) { issue(c + 1, st ^ 1); CP_WAIT1(); }
        else            { CP_WAIT0(); }
        __syncthreads();

        const __nv_bfloat16* Ahi = sAhi[st];
        const __nv_bfloat16* Alo = sAlo[st];
        const __nv_bfloat16* Bhi = sBhi[st];
        const __nv_bfloat16* Blo = sBlo[st];
        #pragma unroll
        for (int ks = 0; ks < 2; ++ks) {      // k16 steps within 32-chunk
            const int kb = ks * 16;
            int rb[4], ra0[4], ra1[4];
            #pragma unroll
            for (int ni = 0; ni < 4; ++ni) rb[ni] = (wn + ni * 8 + tg) * SROW;
            #pragma unroll
            for (int mi = 0; mi < 4; ++mi) {
                ra0[mi] = (wm + mi * 16 + tg) * SROW;
                ra1[mi] = ra0[mi] + 8 * SROW;
            }
            uint32_t bh[4][2], ah[4][4];
            #pragma unroll
            for (int ni = 0; ni < 4; ++ni) {
                bh[ni][0] = *(const uint32_t*)(&Bhi[rb[ni] + kb + 2 * tig]);
                bh[ni][1] = *(const uint32_t*)(&Bhi[rb[ni] + kb + 8 + 2 * tig]);
            }
            #pragma unroll
            for (int mi = 0; mi < 4; ++mi) {
                ah[mi][0] = *(const uint32_t*)(&Ahi[ra0[mi] + kb + 2 * tig]);
                ah[mi][1] = *(const uint32_t*)(&Ahi[ra1[mi] + kb + 2 * tig]);
                ah[mi][2] = *(const uint32_t*)(&Ahi[ra0[mi] + kb + 8 + 2 * tig]);
                ah[mi][3] = *(const uint32_t*)(&Ahi[ra1[mi] + kb + 8 + 2 * tig]);
            }
            // phase hh: Whi * Xhi
            #pragma unroll
            for (int mi = 0; mi < 4; ++mi)
                #pragma unroll
                for (int ni = 0; ni < 4; ++ni)
                    mma16816(acc[mi][ni], ah[mi][0], ah[mi][1], ah[mi][2], ah[mi][3],
                             bh[ni][0], bh[ni][1]);
            // phase hl: Whi * Xlo (reuse ah)
            #pragma unroll
            for (int ni = 0; ni < 4; ++ni) {
                uint32_t bl0 = *(const uint32_t*)(&Blo[rb[ni] + kb + 2 * tig]);
                uint32_t bl1 = *(const uint32_t*)(&Blo[rb[ni] + kb + 8 + 2 * tig]);
                #pragma unroll
                for (int mi = 0; mi < 4; ++mi)
                    mma16816(acc[mi][ni], ah[mi][0], ah[mi][1], ah[mi][2], ah[mi][3],
                             bl0, bl1);
            }
            // phase lh: Wlo * Xhi (reuse bh)
            #pragma unroll
            for (int mi = 0; mi < 4; ++mi) {
                uint32_t al0 = *(const uint32_t*)(&Alo[ra0[mi] + kb + 2 * tig]);
                uint32_t al1 = *(const uint32_t*)(&Alo[ra1[mi] + kb + 2 * tig]);
                uint32_t al2 = *(const uint32_t*)(&Alo[ra0[mi] + kb + 8 + 2 * tig]);
                uint32_t al3 = *(const uint32_t*)(&Alo[ra1[mi] + kb + 8 + 2 * tig]);
                #pragma unroll
                for (int ni = 0; ni < 4; ++ni)
                    mma16816(acc[mi][ni], al0, al1, al2, al3, bh[ni][0], bh[ni][1]);
            }
        }
        __syncthreads();
    }

    // epilogue: store + fused BN stats
    const int bb = (int)(r0 >> 12);            // batch (LAYER2)
    const int n0 = (int)(r0 & (NPTS - 1));     // n offset within batch
    #pragma unroll
    for (int mi = 0; mi < 4; ++mi) {
        const int mg0 = m0 + wm + mi * 16 + tg;
        const int mg1 = mg0 + 8;
        const float bv0 = bias[mg0];
        const float bv1 = bias[mg1];
        float s0 = 0.f, q0 = 0.f, s1 = 0.f, q1 = 0.f;
        #pragma unroll
        for (int ni = 0; ni < 4; ++ni) {
            const float v00 = acc[mi][ni][0] + bv0;
            const float v01 = acc[mi][ni][1] + bv0;
            const float v10 = acc[mi][ni][2] + bv1;
            const float v11 = acc[mi][ni][3] + bv1;
            if (LAYER == 1) {
                const size_t n = r0 + wn + ni * 8 + 2 * tig;
                g_Y1t[n * 256 + mg0]       = v00;
                g_Y1t[(n + 1) * 256 + mg0] = v01;
                g_Y1t[n * 256 + mg1]       = v10;
                g_Y1t[(n + 1) * 256 + mg1] = v11;
            } else {
                const int nloc = n0 + wn + ni * 8 + 2 * tig;
                *(float2*)(outp + ((size_t)bb * 256 + mg0) * NPTS + nloc) =
                    make_float2(v00, v01);
                *(float2*)(outp + ((size_t)bb * 256 + mg1) * NPTS + nloc) =
                    make_float2(v10, v11);
            }
            s0 += v00 + v01; q0 += v00 * v00 + v01 * v01;
            s1 += v10 + v11; q1 += v10 * v10 + v11 * v11;
        }
        #pragma unroll
        for (int off = 1; off <= 2; off <<= 1) {
            s0 += __shfl_xor_sync(0xffffffffu, s0, off);
            q0 += __shfl_xor_sync(0xffffffffu, q0, off);
            s1 += __shfl_xor_sync(0xffffffffu, s1, off);
            q1 += __shfl_xor_sync(0xffffffffu, q1, off);
        }
        if (tig == 0) {
            atomicAdd(&gsum[mg0], s0); atomicAdd(&gsq[mg0], q0);
            atomicAdd(&gsum[mg1], s1); atomicAdd(&gsq[mg1], q1);
        }
    }
}

// ======================= finalize / fold ====================================
template <int LAYER>
__global__ void finalize_kernel(const float* __restrict__ gamma,
                                const float* __restrict__ beta) {
    const float* gsum = (LAYER == 1) ? g_sum1 : g_sum2;
    const float* gsq  = (LAYER == 1) ? g_sumsq1 : g_sumsq2;
    float* scale      = (LAYER == 1) ? g_scale1 : g_scale2;
    float* shift      = (LAYER == 1) ? g_shift1 : g_shift2;
    const int c = threadIdx.x;
    const float inv = 1.0f / (float)((size_t)NT);
    float m  = gsum[c] * inv;
    float v  = fmaxf(gsq[c] * inv - m * m, 0.f);
    float sc = gamma[c] * rsqrtf(v + BN_EPS);
    scale[c] = sc;
    shift[c] = beta[c] - m * sc;
}

// BN1 + ReLU + bf16 split: Y1t [row][256] -> X2hi/X2lo [row][256]
__global__ void convert2_kernel() {
    const int gid = blockIdx.x * 256 + threadIdx.x;       // one per 8 channels
    const size_t r = (size_t)(gid >> 5);
    const int c0 = (gid & 31) * 8;
    const float* p = g_Y1t + r * 256 + c0;
    float4 a = *(const float4*)(p);
    float4 b = *(const float4*)(p + 4);
    float4 s0 = *(const float4*)(g_scale1 + c0);
    float4 s1 = *(const float4*)(g_scale1 + c0 + 4);
    float4 t0 = *(const float4*)(g_shift1 + c0);
    float4 t1 = *(const float4*)(g_shift1 + c0 + 4);
    float v[8];
    v[0] = fmaxf(fmaf(a.x, s0.x, t0.x), 0.f);
    v[1] = fmaxf(fmaf(a.y, s0.y, t0.y), 0.f);
    v[2] = fmaxf(fmaf(a.z, s0.z, t0.z), 0.f);
    v[3] = fmaxf(fmaf(a.w, s0.w, t0.w), 0.f);
    v[4] = fmaxf(fmaf(b.x, s1.x, t1.x), 0.f);
    v[5] = fmaxf(fmaf(b.y, s1.y, t1.y), 0.f);
    v[6] = fmaxf(fmaf(b.z, s1.z, t1.z), 0.f);
    v[7] = fmaxf(fmaf(b.w, s1.w, t1.w), 0.f);
    split8_store(v, g_X2hi + (r * 256 + c0) / 8, g_X2lo + (r * 256 + c0) / 8);
}

// final: BN2 + ReLU in place on out [b][m][n]
__global__ void apply2_kernel(float* __restrict__ out) {
    const int i4 = blockIdx.x * 256 + threadIdx.x;   // float4 index
    const int c  = (i4 >> 10) & 255;                 // NPTS/4 = 1024 f4 per row
    const float s = g_scale2[c], t = g_shift2[c];
    float4 v = ((float4*)out)[i4];
    v.x = fmaxf(fmaf(v.x, s, t), 0.f);
    v.y = fmaxf(fmaf(v.y, s, t), 0.f);
    v.z = fmaxf(fmaf(v.z, s, t), 0.f);
    v.w = fmaxf(fmaf(v.w, s, t), 0.f);
    ((float4*)out)[i4] = v;
}

// ======================= launch =============================================
extern "C" void kernel_launch(void* const* d_in, const int* in_sizes, int n_in,
                              void* d_out, int out_size) {
    const float* feature1 = (const float*)d_in[0];
    const float* coord1   = (const float*)d_in[1];
    const float* feature2 = (const float*)d_in[2];
    const float* coord2   = (const float*)d_in[3];
    const float* W1 = (const float*)d_in[4];
    const float* b1 = (const float*)d_in[5];
    const float* gamma1 = (const float*)d_in[6];
    const float* beta1  = (const float*)d_in[7];
    const float* W2 = (const float*)d_in[8];
    const float* b2 = (const float*)d_in[9];
    const float* gamma2 = (const float*)d_in[10];
    const float* beta2  = (const float*)d_in[11];
    float* out = (float*)d_out;

    init_kernel<<<1, 256>>>();
    convert_w_kernel<<<(CH * CIN + COUT * CH + 255) / 256, 256>>>(W1, W2);
    transpose_f2_kernel<<<dim3(GPTS / 32, D2 / 32, BATCH), dim3(32, 8)>>>(feature2);
    transpose_f1_kernel<<<dim3(NPTS / 32, D1 / 32, BATCH), dim3(32, 8)>>>(feature1);
    knn_search_kernel<<<dim3(NPTS / 64, BATCH), 256>>>(coord1, coord2);
    knn_gather_kernel<<<NT * 32 / 256, 256>>>();

    gemm_mma_kernel<1><<<dim3(2, NT / 128), 256>>>(b1, nullptr);
    finalize_kernel<1><<<1, CH>>>(gamma1, beta1);
    convert2_kernel<<<NT * 32 / 256, 256>>>();

    gemm_mma_kernel<2><<<dim3(2, NT / 128), 256>>>(b2, out);
    finalize_kernel<2><<<1, COUT>>>(gamma2, beta2);

    apply2_kernel<<<(size_t)BATCH * COUT * NPTS / 4 / 256, 256>>>(out);
}

// round 14
// speedup vs baseline: 1.3469x; 1.1828x over previous
#include <cuda_runtime.h>
#include <cuda_fp16.h>
#include <math_constants.h>
#include <cstdint>

#define BATCH 16
#define NPTS  4096
#define GPTS  1024
#define D1    128
#define D2    256
#define CIN   384
#define CH    256
#define COUT  256
#define NT    (BATCH * NPTS)      /* 65536 flat rows */
#define BN_EPS 1e-5f

#define SROW 40                    /* smem row stride in fp16 (80 B), K-chunk 32 */
#define TILEB (128 * SROW * 2)     /* one tile in bytes (10240) */

// ======================= scratch (device globals) ===========================
__device__ uint4 g_X1hi[(size_t)NT * CIN / 8];   // fp16 [NT][384]
__device__ uint4 g_X1lo[(size_t)NT * CIN / 8];
__device__ uint4 g_X2hi[(size_t)NT * CH / 8];    // fp16 [NT][256]
__device__ uint4 g_X2lo[(size_t)NT * CH / 8];
__device__ float g_Y1t[(size_t)NT * CH];          // fp32 [NT][256]
__device__ float g_f2t[(size_t)BATCH * GPTS * D2];
__device__ float4 g_knnw[NT];                     // (w0,w1,w2,-)
__device__ int4   g_knni[NT];                     // (i0,i1,i2,-)
__device__ uint4 g_W1hi[CH * CIN / 8];            // fp16 [256][384]
__device__ uint4 g_W2hi[COUT * CH / 8];           // fp16 [256][256]
__device__ float g_sum1[CH],   g_sumsq1[CH];
__device__ float g_sum2[COUT], g_sumsq2[COUT];
__device__ float g_scale1[CH],   g_shift1[CH];
__device__ float g_scale2[COUT], g_shift2[COUT];

// ======================= asm helpers ========================================
__device__ __forceinline__ uint32_t smem_u32(const void* p) {
    uint32_t a;
    asm("{ .reg .u64 t; cvta.to.shared.u64 t, %1; cvt.u32.u64 %0, t; }"
        : "=r"(a) : "l"(p));
    return a;
}

#define CPA16(dst_u32, src_ptr) \
    asm volatile("cp.async.cg.shared.global [%0], [%1], 16;" \
                 :: "r"(dst_u32), "l"(src_ptr) : "memory")
#define CP_COMMIT() asm volatile("cp.async.commit_group;" ::: "memory")
#define CP_WAIT1()  asm volatile("cp.async.wait_group 1;" ::: "memory")
#define CP_WAIT0()  asm volatile("cp.async.wait_group 0;" ::: "memory")

__device__ __forceinline__ void mma16816(float c[4],
                                         uint32_t a0, uint32_t a1, uint32_t a2, uint32_t a3,
                                         uint32_t b0, uint32_t b1) {
    asm volatile(
        "mma.sync.aligned.m16n8k16.row.col.f32.f16.f16.f32 "
        "{%0,%1,%2,%3}, {%4,%5,%6,%7}, {%8,%9}, {%0,%1,%2,%3};"
        : "+f"(c[0]), "+f"(c[1]), "+f"(c[2]), "+f"(c[3])
        : "r"(a0), "r"(a1), "r"(a2), "r"(a3), "r"(b0), "r"(b1));
}

// ======================= small kernels ======================================
__global__ void init_kernel() {
    int t = threadIdx.x;
    g_sum1[t] = 0.f; g_sumsq1[t] = 0.f;
    g_sum2[t] = 0.f; g_sumsq2[t] = 0.f;
}

__device__ __forceinline__ void split1(float v, __half& h, __half& l) {
    h = __float2half(v);
    l = __float2half(v - __half2float(h));
}

__global__ void convert_w_kernel(const float* __restrict__ W1,
                                 const float* __restrict__ W2) {
    int i = blockIdx.x * blockDim.x + threadIdx.x;
    const int t1 = CH * CIN;
    const int t2 = COUT * CH;
    if (i < t1) {
        ((__half*)g_W1hi)[i] = __float2half(W1[i]);
    } else if (i < t1 + t2) {
        int j = i - t1;
        ((__half*)g_W2hi)[j] = __float2half(W2[j]);
    }
}

// transpose feature2: [B][D2][G] -> [B][G][D2]  (fp32)
__global__ void transpose_f2_kernel(const float* __restrict__ f2) {
    __shared__ float tile[32][33];
    int b  = blockIdx.z;
    int g0 = blockIdx.x * 32;
    int d0 = blockIdx.y * 32;
    const float* src = f2 + (size_t)b * D2 * GPTS;
    #pragma unroll
    for (int r = threadIdx.y; r < 32; r += 8)
        tile[r][threadIdx.x] = src[(size_t)(d0 + r) * GPTS + g0 + threadIdx.x];
    __syncthreads();
    float* dst = g_f2t + (size_t)b * GPTS * D2;
    #pragma unroll
    for (int r = threadIdx.y; r < 32; r += 8)
        dst[(size_t)(g0 + r) * D2 + d0 + threadIdx.x] = tile[threadIdx.x][r];
}

// transpose feature1: [B][D1][N] -> X1 rows [row][0:128] (fp16 hi/lo)
__global__ void transpose_f1_kernel(const float* __restrict__ f1) {
    __shared__ float tile[32][33];
    const int b  = blockIdx.z;
    const int n0 = blockIdx.x * 32;
    const int d0 = blockIdx.y * 32;
    const float* src = f1 + (size_t)b * D1 * NPTS;
    #pragma unroll
    for (int r = threadIdx.y; r < 32; r += 8)
        tile[r][threadIdx.x] = src[(size_t)(d0 + r) * NPTS + n0 + threadIdx.x];
    __syncthreads();
    __half* hi = (__half*)g_X1hi;
    __half* lo = (__half*)g_X1lo;
    #pragma unroll
    for (int i = threadIdx.y; i < 32; i += 8) {
        const size_t row = (size_t)b * NPTS + n0 + i;
        __half h, l;
        split1(tile[threadIdx.x][i], h, l);
        hi[row * CIN + d0 + threadIdx.x] = h;
        lo[row * CIN + d0 + threadIdx.x] = l;
    }
}

__device__ __forceinline__ void split8_store(const float v[8], uint4* hip, uint4* lop) {
    uint32_t h[4], l[4];
    #pragma unroll
    for (int i = 0; i < 4; ++i) {
        __half h0, l0, h1, l1;
        split1(v[2 * i], h0, l0);
        split1(v[2 * i + 1], h1, l1);
        h[i] = (uint32_t)__half_as_ushort(h0) | ((uint32_t)__half_as_ushort(h1) << 16);
        l[i] = (uint32_t)__half_as_ushort(l0) | ((uint32_t)__half_as_ushort(l1) << 16);
    }
    *hip = make_uint4(h[0], h[1], h[2], h[3]);
    *lop = make_uint4(l[0], l[1], l[2], l[3]);
}

// 3-NN search only: 8 lanes x 2 points per group. Block 256 = 32 groups.
__global__ void knn_search_kernel(const float* __restrict__ coord1,
                                  const float* __restrict__ coord2) {
    __shared__ float4 s2[GPTS];
    const int b   = blockIdx.y;
    const int tid = threadIdx.x;
    const int q   = tid & 7;                        // lane within group
    const int nb  = blockIdx.x * 64 + (tid >> 3) * 2;   // first of 2 points

    const float* c2 = coord2 + (size_t)b * 3 * GPTS;
    for (int g = tid; g < GPTS; g += 256) {
        float x = c2[g], y = c2[GPTS + g], z = c2[2 * GPTS + g];
        s2[g] = make_float4(x, y, z, -0.5f * (x * x + y * y + z * z));
    }
    __syncthreads();

    const float* c1 = coord1 + (size_t)b * 3 * NPTS;
    float2 pxv = *(const float2*)(c1 + nb);
    float2 pyv = *(const float2*)(c1 + NPTS + nb);
    float2 pzv = *(const float2*)(c1 + 2 * NPTS + nb);
    const float px[2] = {pxv.x, pxv.y};
    const float py[2] = {pyv.x, pyv.y};
    const float pz[2] = {pzv.x, pzv.y};

    float e0[2], e1[2], e2[2];
    int   i0[2], i1[2], i2[2];
    #pragma unroll
    for (int p = 0; p < 2; ++p) {
        e0[p] = e1[p] = e2[p] = -CUDART_INF_F;
        i0[p] = i1[p] = i2[p] = 0;
    }

    #pragma unroll 4
    for (int it = 0; it < GPTS / 8; ++it) {
        const int g = q + it * 8;
        const float4 c = s2[g];
        #pragma unroll
        for (int p = 0; p < 2; ++p) {
            float e = fmaf(px[p], c.x, fmaf(py[p], c.y, fmaf(pz[p], c.z, c.w)));
            if (e > e2[p]) {
                if (e > e1[p]) {
                    e2[p] = e1[p]; i2[p] = i1[p];
                    if (e > e0[p]) { e1[p] = e0[p]; i1[p] = i0[p]; e0[p] = e; i0[p] = g; }
                    else           { e1[p] = e; i1[p] = g; }
                } else { e2[p] = e; i2[p] = g; }
            }
        }
    }

    #pragma unroll
    for (int off = 1; off <= 4; off <<= 1) {
        #pragma unroll
        for (int p = 0; p < 2; ++p) {
            float f0 = __shfl_xor_sync(0xffffffffu, e0[p], off);
            float f1 = __shfl_xor_sync(0xffffffffu, e1[p], off);
            float f2 = __shfl_xor_sync(0xffffffffu, e2[p], off);
            int   j0 = __shfl_xor_sync(0xffffffffu, i0[p], off);
            int   j1 = __shfl_xor_sync(0xffffffffu, i1[p], off);
            int   j2 = __shfl_xor_sync(0xffffffffu, i2[p], off);
            float m0, m1, m2; int k0, k1, k2;
            if (e0[p] >= f0) {
                m0 = e0[p]; k0 = i0[p];
                if (e1[p] >= f0) {
                    m1 = e1[p]; k1 = i1[p];
                    if (e2[p] >= f0) { m2 = e2[p]; k2 = i2[p]; } else { m2 = f0; k2 = j0; }
                } else {
                    m1 = f0; k1 = j0;
                    if (e1[p] >= f1) { m2 = e1[p]; k2 = i1[p]; } else { m2 = f1; k2 = j1; }
                }
            } else {
                m0 = f0; k0 = j0;
                if (f1 >= e0[p]) {
                    m1 = f1; k1 = j1;
                    if (f2 >= e0[p]) { m2 = f2; k2 = j2; } else { m2 = e0[p]; k2 = i0[p]; }
                } else {
                    m1 = e0[p]; k1 = i0[p];
                    if (f1 >= e1[p]) { m2 = f1; k2 = j1; } else { m2 = e1[p]; k2 = i1[p]; }
                }
            }
            e0[p] = m0; i0[p] = k0; e1[p] = m1; i1[p] = k1; e2[p] = m2; i2[p] = k2;
        }
    }

    if (q == 0) {
        #pragma unroll
        for (int p = 0; p < 2; ++p) {
            const float qn = px[p] * px[p] + py[p] * py[p] + pz[p] * pz[p];
            const float d0 = qn - 2.0f * e0[p];
            const float d1 = qn - 2.0f * e1[p];
            const float d2 = qn - 2.0f * e2[p];
            const float r0w = 1.0f / (d0 + 1e-8f);
            const float r1w = 1.0f / (d1 + 1e-8f);
            const float r2w = 1.0f / (d2 + 1e-8f);
            const float rs = 1.0f / (r0w + r1w + r2w);
            const size_t row = (size_t)b * NPTS + nb + p;
            g_knnw[row] = make_float4(r0w * rs, r1w * rs, r2w * rs, 0.f);
            g_knni[row] = make_int4(i0[p], i1[p], i2[p], 0);
        }
    }
}

// gather + interp: one warp per point; lane c handles interp chunk c (0..31).
__global__ void knn_gather_kernel() {
    const int gid = blockIdx.x * 256 + threadIdx.x;
    const size_t r = (size_t)(gid >> 5);      // point row
    const int c = gid & 31;                   // d8 chunk within D2
    const int b = (int)(r >> 12);

    const float4 w = g_knnw[r];
    const int4  ii = g_knni[r];
    const float* F = g_f2t + (size_t)b * GPTS * D2;
    const float4* p0 = (const float4*)(F + (size_t)ii.x * D2);
    const float4* p1 = (const float4*)(F + (size_t)ii.y * D2);
    const float4* p2 = (const float4*)(F + (size_t)ii.z * D2);

    float4 a0 = p0[2 * c], a1 = p0[2 * c + 1];
    float4 b0 = p1[2 * c], b1 = p1[2 * c + 1];
    float4 g0 = p2[2 * c], g1 = p2[2 * c + 1];
    float v[8];
    v[0] = w.x * a0.x + w.y * b0.x + w.z * g0.x;
    v[1] = w.x * a0.y + w.y * b0.y + w.z * g0.y;
    v[2] = w.x * a0.z + w.y * b0.z + w.z * g0.z;
    v[3] = w.x * a0.w + w.y * b0.w + w.z * g0.w;
    v[4] = w.x * a1.x + w.y * b1.x + w.z * g1.x;
    v[5] = w.x * a1.y + w.y * b1.y + w.z * g1.y;
    v[6] = w.x * a1.z + w.y * b1.z + w.z * g1.z;
    v[7] = w.x * a1.w + w.y * b1.w + w.z * g1.w;
    split8_store(v, g_X1hi + r * (CIN / 8) + D1 / 8 + c,
                    g_X1lo + r * (CIN / 8) + D1 / 8 + c);
}

// ======================= HMMA GEMM (fp16, 2 phases, 3-stage pipeline) =======
// C[m][n] = Whi*Xhi + Whi*Xlo per K32 chunk (fp16 hi/lo split on X; W single
// fp16 — error ~3e-4 relative, well under 1e-3). CTA tile 128(M)x128(N),
// 3-stage cp.async with ONE __syncthreads per chunk (writer targets the stage
// two behind the reader). 8 warps = 2(M)x4(N).
// LAYER1 epilogue -> g_Y1t[n][m]; LAYER2 -> out[b][m][n]. BN stats fused.
template <int LAYER>
__global__ void __launch_bounds__(256, 2)
gemm_mma_kernel(const float* __restrict__ bias, float* __restrict__ outp) {
    constexpr int K0 = (LAYER == 1) ? CIN : CH;
    constexpr int NC = K0 / 32;

    const __half* Whi = (LAYER == 1) ? (const __half*)g_W1hi : (const __half*)g_W2hi;
    const __half* Xhi = (LAYER == 1) ? (const __half*)g_X1hi : (const __half*)g_X2hi;
    const __half* Xlo = (LAYER == 1) ? (const __half*)g_X1lo : (const __half*)g_X2lo;
    float* gsum  = (LAYER == 1) ? g_sum1 : g_sum2;
    float* gsq   = (LAYER == 1) ? g_sumsq1 : g_sumsq2;

    __shared__ __align__(16) __half sAhi[3][128 * SROW];
    __shared__ __align__(16) __half sBhi[3][128 * SROW];
    __shared__ __align__(16) __half sBlo[3][128 * SROW];

    const int tid  = threadIdx.x;
    const int wid  = tid >> 5, lane = tid & 31;
    const int tg   = lane >> 2;            // groupID (0..7)
    const int tig  = lane & 3;             // threadID_in_group (0..3)
    const size_t r0 = (size_t)blockIdx.x * 128;   // X row block
    const int m0 = blockIdx.y * 128;              // W row block
    const int wm = (wid & 1) * 64;
    const int wn = (wid >> 1) * 32;

    const uint32_t aAhi = smem_u32(sAhi);
    const uint32_t aBhi = smem_u32(sBhi);
    const uint32_t aBlo = smem_u32(sBlo);
    const int ldr  = tid >> 2;             // load row (0..63), +64 second half
    const int ldch = tid & 3;              // 16B chunk in row (32 cols = 4)
    const uint32_t ldoff = (uint32_t)(ldr * SROW * 2 + ldch * 16);

    float acc[4][4][4];
    #pragma unroll
    for (int i = 0; i < 4; ++i)
        #pragma unroll
        for (int j = 0; j < 4; ++j)
            #pragma unroll
            for (int k = 0; k < 4; ++k) acc[i][j][k] = 0.f;

    auto issue = [&](int c, int st) {
        const int kk = c * 32;
        const uint32_t so = (uint32_t)st * TILEB + ldoff;
        #pragma unroll
        for (int i = 0; i < 2; ++i) {
            const int r = ldr + i * 64;
            const uint32_t d = so + (uint32_t)(i * 64 * SROW * 2);
            CPA16(aAhi + d, Whi + (size_t)(m0 + r) * K0 + kk + ldch * 8);
            CPA16(aBhi + d, Xhi + (r0 + r) * K0 + kk + ldch * 8);
            CPA16(aBlo + d, Xlo + (r0 + r) * K0 + kk + ldch * 8);
        }
        CP_COMMIT();
    };

    issue(0, 0);
    if (NC > 1) issue(1, 1);
    for (int c = 0; c < NC; ++c) {
        if (c + 1 < NC) CP_WAIT1(); else CP_WAIT0();
        __syncthreads();
        if (c + 2 < NC) issue(c + 2, (c + 2) % 3);

        const int st = c % 3;
        const __half* Ahi = sAhi[st];
        const __half* Bhi = sBhi[st];
        const __half* Blo = sBlo[st];
        #pragma unroll
        for (int ks = 0; ks < 2; ++ks) {      // k16 steps within 32-chunk
            const int kb = ks * 16;
            int rb[4], ra0[4], ra1[4];
            #pragma unroll
            for (int ni = 0; ni < 4; ++ni) rb[ni] = (wn + ni * 8 + tg) * SROW;
            #pragma unroll
            for (int mi = 0; mi < 4; ++mi) {
                ra0[mi] = (wm + mi * 16 + tg) * SROW;
                ra1[mi] = ra0[mi] + 8 * SROW;
            }
            uint32_t bh[4][2], ah[4][4];
            #pragma unroll
            for (int ni = 0; ni < 4; ++ni) {
                bh[ni][0] = *(const uint32_t*)(&Bhi[rb[ni] + kb + 2 * tig]);
                bh[ni][1] = *(const uint32_t*)(&Bhi[rb[ni] + kb + 8 + 2 * tig]);
            }
            #pragma unroll
            for (int mi = 0; mi < 4; ++mi) {
                ah[mi][0] = *(const uint32_t*)(&Ahi[ra0[mi] + kb + 2 * tig]);
                ah[mi][1] = *(const uint32_t*)(&Ahi[ra1[mi] + kb + 2 * tig]);
                ah[mi][2] = *(const uint32_t*)(&Ahi[ra0[mi] + kb + 8 + 2 * tig]);
                ah[mi][3] = *(const uint32_t*)(&Ahi[ra1[mi] + kb + 8 + 2 * tig]);
            }
            // phase hh: Whi * Xhi
            #pragma unroll
            for (int mi = 0; mi < 4; ++mi)
                #pragma unroll
                for (int ni = 0; ni < 4; ++ni)
                    mma16816(acc[mi][ni], ah[mi][0], ah[mi][1], ah[mi][2], ah[mi][3],
                             bh[ni][0], bh[ni][1]);
            // phase hl: Whi * Xlo (reuse ah)
            #pragma unroll
            for (int ni = 0; ni < 4; ++ni) {
                uint32_t bl0 = *(const uint32_t*)(&Blo[rb[ni] + kb + 2 * tig]);
                uint32_t bl1 = *(const uint32_t*)(&Blo[rb[ni] + kb + 8 + 2 * tig]);
                #pragma unroll
                for (int mi = 0; mi < 4; ++mi)
                    mma16816(acc[mi][ni], ah[mi][0], ah[mi][1], ah[mi][2], ah[mi][3],
                             bl0, bl1);
            }
        }
    }
    __syncthreads();

    // epilogue: store + fused BN stats
    const int bb = (int)(r0 >> 12);            // batch (LAYER2)
    const int n0 = (int)(r0 & (NPTS - 1));     // n offset within batch
    #pragma unroll
    for (int mi = 0; mi < 4; ++mi) {
        const int mg0 = m0 + wm + mi * 16 + tg;
        const int mg1 = mg0 + 8;
        const float bv0 = bias[mg0];
        const float bv1 = bias[mg1];
        float s0 = 0.f, q0 = 0.f, s1 = 0.f, q1 = 0.f;
        #pragma unroll
        for (int ni = 0; ni < 4; ++ni) {
            const float v00 = acc[mi][ni][0] + bv0;
            const float v01 = acc[mi][ni][1] + bv0;
            const float v10 = acc[mi][ni][2] + bv1;
            const float v11 = acc[mi][ni][3] + bv1;
            if (LAYER == 1) {
                const size_t n = r0 + wn + ni * 8 + 2 * tig;
                g_Y1t[n * 256 + mg0]       = v00;
                g_Y1t[(n + 1) * 256 + mg0] = v01;
                g_Y1t[n * 256 + mg1]       = v10;
                g_Y1t[(n + 1) * 256 + mg1] = v11;
            } else {
                const int nloc = n0 + wn + ni * 8 + 2 * tig;
                *(float2*)(outp + ((size_t)bb * 256 + mg0) * NPTS + nloc) =
                    make_float2(v00, v01);
                *(float2*)(outp + ((size_t)bb * 256 + mg1) * NPTS + nloc) =
                    make_float2(v10, v11);
            }
            s0 += v00 + v01; q0 += v00 * v00 + v01 * v01;
            s1 += v10 + v11; q1 += v10 * v10 + v11 * v11;
        }
        #pragma unroll
        for (int off = 1; off <= 2; off <<= 1) {
            s0 += __shfl_xor_sync(0xffffffffu, s0, off);
            q0 += __shfl_xor_sync(0xffffffffu, q0, off);
            s1 += __shfl_xor_sync(0xffffffffu, s1, off);
            q1 += __shfl_xor_sync(0xffffffffu, q1, off);
        }
        if (tig == 0) {
            atomicAdd(&gsum[mg0], s0); atomicAdd(&gsq[mg0], q0);
            atomicAdd(&gsum[mg1], s1); atomicAdd(&gsq[mg1], q1);
        }
    }
}

// ======================= finalize / fold ====================================
template <int LAYER>
__global__ void finalize_kernel(const float* __restrict__ gamma,
                                const float* __restrict__ beta) {
    const float* gsum = (LAYER == 1) ? g_sum1 : g_sum2;
    const float* gsq  = (LAYER == 1) ? g_sumsq1 : g_sumsq2;
    float* scale      = (LAYER == 1) ? g_scale1 : g_scale2;
    float* shift      = (LAYER == 1) ? g_shift1 : g_shift2;
    const int c = threadIdx.x;
    const float inv = 1.0f / (float)((size_t)NT);
    float m  = gsum[c] * inv;
    float v  = fmaxf(gsq[c] * inv - m * m, 0.f);
    float sc = gamma[c] * rsqrtf(v + BN_EPS);
    scale[c] = sc;
    shift[c] = beta[c] - m * sc;
}

// BN1 + ReLU + fp16 split: Y1t [row][256] -> X2hi/X2lo [row][256]
__global__ void convert2_kernel() {
    const int gid = blockIdx.x * 256 + threadIdx.x;       // one per 8 channels
    const size_t r = (size_t)(gid >> 5);
    const int c0 = (gid & 31) * 8;
    const float* p = g_Y1t + r * 256 + c0;
    float4 a = *(const float4*)(p);
    float4 b = *(const float4*)(p + 4);
    float4 s0 = *(const float4*)(g_scale1 + c0);
    float4 s1 = *(const float4*)(g_scale1 + c0 + 4);
    float4 t0 = *(const float4*)(g_shift1 + c0);
    float4 t1 = *(const float4*)(g_shift1 + c0 + 4);
    float v[8];
    v[0] = fmaxf(fmaf(a.x, s0.x, t0.x), 0.f);
    v[1] = fmaxf(fmaf(a.y, s0.y, t0.y), 0.f);
    v[2] = fmaxf(fmaf(a.z, s0.z, t0.z), 0.f);
    v[3] = fmaxf(fmaf(a.w, s0.w, t0.w), 0.f);
    v[4] = fmaxf(fmaf(b.x, s1.x, t1.x), 0.f);
    v[5] = fmaxf(fmaf(b.y, s1.y, t1.y), 0.f);
    v[6] = fmaxf(fmaf(b.z, s1.z, t1.z), 0.f);
    v[7] = fmaxf(fmaf(b.w, s1.w, t1.w), 0.f);
    split8_store(v, g_X2hi + (r * 256 + c0) / 8, g_X2lo + (r * 256 + c0) / 8);
}

// final: BN2 + ReLU in place on out [b][m][n]
__global__ void apply2_kernel(float* __restrict__ out) {
    const int i4 = blockIdx.x * 256 + threadIdx.x;   // float4 index
    const int c  = (i4 >> 10) & 255;                 // NPTS/4 = 1024 f4 per row
    const float s = g_scale2[c], t = g_shift2[c];
    float4 v = ((float4*)out)[i4];
    v.x = fmaxf(fmaf(v.x, s, t), 0.f);
    v.y = fmaxf(fmaf(v.y, s, t), 0.f);
    v.z = fmaxf(fmaf(v.z, s, t), 0.f);
    v.w = fmaxf(fmaf(v.w, s, t), 0.f);
    ((float4*)out)[i4] = v;
}

// ======================= launch =============================================
extern "C" void kernel_launch(void* const* d_in, const int* in_sizes, int n_in,
                              void* d_out, int out_size) {
    const float* feature1 = (const float*)d_in[0];
    const float* coord1   = (const float*)d_in[1];
    const float* feature2 = (const float*)d_in[2];
    const float* coord2   = (const float*)d_in[3];
    const float* W1 = (const float*)d_in[4];
    const float* b1 = (const float*)d_in[5];
    const float* gamma1 = (const float*)d_in[6];
    const float* beta1  = (const float*)d_in[7];
    const float* W2 = (const float*)d_in[8];
    const float* b2 = (const float*)d_in[9];
    const float* gamma2 = (const float*)d_in[10];
    const float* beta2  = (const float*)d_in[11];
    float* out = (float*)d_out;

    init_kernel<<<1, 256>>>();
    convert_w_kernel<<<(CH * CIN + COUT * CH + 255) / 256, 256>>>(W1, W2);
    transpose_f2_kernel<<<dim3(GPTS / 32, D2 / 32, BATCH), dim3(32, 8)>>>(feature2);
    transpose_f1_kernel<<<dim3(NPTS / 32, D1 / 32, BATCH), dim3(32, 8)>>>(feature1);
    knn_search_kernel<<<dim3(NPTS / 64, BATCH), 256>>>(coord1, coord2);
    knn_gather_kernel<<<NT * 32 / 256, 256>>>();

    gemm_mma_kernel<1><<<dim3(NT / 128, 2), 256>>>(b1, nullptr);
    finalize_kernel<1><<<1, CH>>>(gamma1, beta1);
    convert2_kernel<<<NT * 32 / 256, 256>>>();

    gemm_mma_kernel<2><<<dim3(NT / 128, 2), 256>>>(b2, out);
    finalize_kernel<2><<<1, COUT>>>(gamma2, beta2);

    apply2_kernel<<<(size_t)BATCH * COUT * NPTS / 4 / 256, 256>>>(out);
}

// round 15
// speedup vs baseline: 1.6438x; 1.2204x over previous
#include <cuda_runtime.h>
#include <cuda_fp16.h>
#include <math_constants.h>
#include <cstdint>

#define BATCH 16
#define NPTS  4096
#define GPTS  1024
#define D1    128
#define D2    256
#define CIN   384
#define CH    256
#define COUT  256
#define NT    (BATCH * NPTS)      /* 65536 flat rows */
#define BN_EPS 1e-5f

#define SROW 40                    /* smem row stride in fp16 (80 B), K-chunk 32 */
#define TILEB (128 * SROW * 2)     /* one tile in bytes (10240) */

// ======================= scratch (device globals) ===========================
__device__ uint4 g_X1[(size_t)NT * CIN / 8];     // fp16 [NT][384]
__device__ uint4 g_X2[(size_t)NT * CH / 8];      // fp16 [NT][256]
__device__ float g_Y1t[(size_t)NT * CH];          // fp32 [NT][256]
__device__ float g_f2t[(size_t)BATCH * GPTS * D2];
__device__ float4 g_knnw[NT];                     // (w0,w1,w2,-)
__device__ int4   g_knni[NT];                     // (i0,i1,i2,-)
__device__ uint4 g_W1h[CH * CIN / 8];             // fp16 [256][384]
__device__ uint4 g_W2h[COUT * CH / 8];            // fp16 [256][256]
__device__ float g_sum1[CH],   g_sumsq1[CH];
__device__ float g_sum2[COUT], g_sumsq2[COUT];
__device__ float g_scale1[CH],   g_shift1[CH];
__device__ float g_scale2[COUT], g_shift2[COUT];

// ======================= asm helpers ========================================
__device__ __forceinline__ uint32_t smem_u32(const void* p) {
    uint32_t a;
    asm("{ .reg .u64 t; cvta.to.shared.u64 t, %1; cvt.u32.u64 %0, t; }"
        : "=r"(a) : "l"(p));
    return a;
}

#define CPA16(dst_u32, src_ptr) \
    asm volatile("cp.async.cg.shared.global [%0], [%1], 16;" \
                 :: "r"(dst_u32), "l"(src_ptr) : "memory")
#define CP_COMMIT() asm volatile("cp.async.commit_group;" ::: "memory")
#define CP_WAIT1()  asm volatile("cp.async.wait_group 1;" ::: "memory")
#define CP_WAIT0()  asm volatile("cp.async.wait_group 0;" ::: "memory")

__device__ __forceinline__ void mma16816(float c[4],
                                         uint32_t a0, uint32_t a1, uint32_t a2, uint32_t a3,
                                         uint32_t b0, uint32_t b1) {
    asm volatile(
        "mma.sync.aligned.m16n8k16.row.col.f32.f16.f16.f32 "
        "{%0,%1,%2,%3}, {%4,%5,%6,%7}, {%8,%9}, {%0,%1,%2,%3};"
        : "+f"(c[0]), "+f"(c[1]), "+f"(c[2]), "+f"(c[3])
        : "r"(a0), "r"(a1), "r"(a2), "r"(a3), "r"(b0), "r"(b1));
}

// ======================= small kernels ======================================
__global__ void init_kernel() {
    int t = threadIdx.x;
    g_sum1[t] = 0.f; g_sumsq1[t] = 0.f;
    g_sum2[t] = 0.f; g_sumsq2[t] = 0.f;
}

__global__ void convert_w_kernel(const float* __restrict__ W1,
                                 const float* __restrict__ W2) {
    int i = blockIdx.x * blockDim.x + threadIdx.x;
    const int t1 = CH * CIN;
    const int t2 = COUT * CH;
    if (i < t1) {
        ((__half*)g_W1h)[i] = __float2half(W1[i]);
    } else if (i < t1 + t2) {
        int j = i - t1;
        ((__half*)g_W2h)[j] = __float2half(W2[j]);
    }
}

// transpose feature2: [B][D2][G] -> [B][G][D2]  (fp32)
__global__ void transpose_f2_kernel(const float* __restrict__ f2) {
    __shared__ float tile[32][33];
    int b  = blockIdx.z;
    int g0 = blockIdx.x * 32;
    int d0 = blockIdx.y * 32;
    const float* src = f2 + (size_t)b * D2 * GPTS;
    #pragma unroll
    for (int r = threadIdx.y; r < 32; r += 8)
        tile[r][threadIdx.x] = src[(size_t)(d0 + r) * GPTS + g0 + threadIdx.x];
    __syncthreads();
    float* dst = g_f2t + (size_t)b * GPTS * D2;
    #pragma unroll
    for (int r = threadIdx.y; r < 32; r += 8)
        dst[(size_t)(g0 + r) * D2 + d0 + threadIdx.x] = tile[threadIdx.x][r];
}

// transpose feature1: [B][D1][N] -> X1 rows [row][0:128] (fp16)
__global__ void transpose_f1_kernel(const float* __restrict__ f1) {
    __shared__ float tile[32][33];
    const int b  = blockIdx.z;
    const int n0 = blockIdx.x * 32;
    const int d0 = blockIdx.y * 32;
    const float* src = f1 + (size_t)b * D1 * NPTS;
    #pragma unroll
    for (int r = threadIdx.y; r < 32; r += 8)
        tile[r][threadIdx.x] = src[(size_t)(d0 + r) * NPTS + n0 + threadIdx.x];
    __syncthreads();
    __half* hi = (__half*)g_X1;
    #pragma unroll
    for (int i = threadIdx.y; i < 32; i += 8) {
        const size_t row = (size_t)b * NPTS + n0 + i;
        hi[row * CIN + d0 + threadIdx.x] = __float2half(tile[threadIdx.x][i]);
    }
}

__device__ __forceinline__ void pack8_store(const float v[8], uint4* hip) {
    uint32_t h[4];
    #pragma unroll
    for (int i = 0; i < 4; ++i) {
        __half h0 = __float2half(v[2 * i]);
        __half h1 = __float2half(v[2 * i + 1]);
        h[i] = (uint32_t)__half_as_ushort(h0) | ((uint32_t)__half_as_ushort(h1) << 16);
    }
    *hip = make_uint4(h[0], h[1], h[2], h[3]);
}

// 3-NN search only: 8 lanes x 2 points per group. Block 256 = 32 groups.
__global__ void knn_search_kernel(const float* __restrict__ coord1,
                                  const float* __restrict__ coord2) {
    __shared__ float4 s2[GPTS];
    const int b   = blockIdx.y;
    const int tid = threadIdx.x;
    const int q   = tid & 7;                        // lane within group
    const int nb  = blockIdx.x * 64 + (tid >> 3) * 2;   // first of 2 points

    const float* c2 = coord2 + (size_t)b * 3 * GPTS;
    for (int g = tid; g < GPTS; g += 256) {
        float x = c2[g], y = c2[GPTS + g], z = c2[2 * GPTS + g];
        s2[g] = make_float4(x, y, z, -0.5f * (x * x + y * y + z * z));
    }
    __syncthreads();

    const float* c1 = coord1 + (size_t)b * 3 * NPTS;
    float2 pxv = *(const float2*)(c1 + nb);
    float2 pyv = *(const float2*)(c1 + NPTS + nb);
    float2 pzv = *(const float2*)(c1 + 2 * NPTS + nb);
    const float px[2] = {pxv.x, pxv.y};
    const float py[2] = {pyv.x, pyv.y};
    const float pz[2] = {pzv.x, pzv.y};

    float e0[2], e1[2], e2[2];
    int   i0[2], i1[2], i2[2];
    #pragma unroll
    for (int p = 0; p < 2; ++p) {
        e0[p] = e1[p] = e2[p] = -CUDART_INF_F;
        i0[p] = i1[p] = i2[p] = 0;
    }

    #pragma unroll 4
    for (int it = 0; it < GPTS / 8; ++it) {
        const int g = q + it * 8;
        const float4 c = s2[g];
        #pragma unroll
        for (int p = 0; p < 2; ++p) {
            float e = fmaf(px[p], c.x, fmaf(py[p], c.y, fmaf(pz[p], c.z, c.w)));
            if (e > e2[p]) {
                if (e > e1[p]) {
                    e2[p] = e1[p]; i2[p] = i1[p];
                    if (e > e0[p]) { e1[p] = e0[p]; i1[p] = i0[p]; e0[p] = e; i0[p] = g; }
                    else           { e1[p] = e; i1[p] = g; }
                } else { e2[p] = e; i2[p] = g; }
            }
        }
    }

    #pragma unroll
    for (int off = 1; off <= 4; off <<= 1) {
        #pragma unroll
        for (int p = 0; p < 2; ++p) {
            float f0 = __shfl_xor_sync(0xffffffffu, e0[p], off);
            float f1 = __shfl_xor_sync(0xffffffffu, e1[p], off);
            float f2 = __shfl_xor_sync(0xffffffffu, e2[p], off);
            int   j0 = __shfl_xor_sync(0xffffffffu, i0[p], off);
            int   j1 = __shfl_xor_sync(0xffffffffu, i1[p], off);
            int   j2 = __shfl_xor_sync(0xffffffffu, i2[p], off);
            float m0, m1, m2; int k0, k1, k2;
            if (e0[p] >= f0) {
                m0 = e0[p]; k0 = i0[p];
                if (e1[p] >= f0) {
                    m1 = e1[p]; k1 = i1[p];
                    if (e2[p] >= f0) { m2 = e2[p]; k2 = i2[p]; } else { m2 = f0; k2 = j0; }
                } else {
                    m1 = f0; k1 = j0;
                    if (e1[p] >= f1) { m2 = e1[p]; k2 = i1[p]; } else { m2 = f1; k2 = j1; }
                }
            } else {
                m0 = f0; k0 = j0;
                if (f1 >= e0[p]) {
                    m1 = f1; k1 = j1;
                    if (f2 >= e0[p]) { m2 = f2; k2 = j2; } else { m2 = e0[p]; k2 = i0[p]; }
                } else {
                    m1 = e0[p]; k1 = i0[p];
                    if (f1 >= e1[p]) { m2 = f1; k2 = j1; } else { m2 = e1[p]; k2 = i1[p]; }
                }
            }
            e0[p] = m0; i0[p] = k0; e1[p] = m1; i1[p] = k1; e2[p] = m2; i2[p] = k2;
        }
    }

    if (q == 0) {
        #pragma unroll
        for (int p = 0; p < 2; ++p) {
            const float qn = px[p] * px[p] + py[p] * py[p] + pz[p] * pz[p];
            const float d0 = qn - 2.0f * e0[p];
            const float d1 = qn - 2.0f * e1[p];
            const float d2 = qn - 2.0f * e2[p];
            const float r0w = 1.0f / (d0 + 1e-8f);
            const float r1w = 1.0f / (d1 + 1e-8f);
            const float r2w = 1.0f / (d2 + 1e-8f);
            const float rs = 1.0f / (r0w + r1w + r2w);
            const size_t row = (size_t)b * NPTS + nb + p;
            g_knnw[row] = make_float4(r0w * rs, r1w * rs, r2w * rs, 0.f);
            g_knni[row] = make_int4(i0[p], i1[p], i2[p], 0);
        }
    }
}

// gather + interp: one warp per point; lane c handles interp chunk c (0..31).
__global__ void knn_gather_kernel() {
    const int gid = blockIdx.x * 256 + threadIdx.x;
    const size_t r = (size_t)(gid >> 5);      // point row
    const int c = gid & 31;                   // d8 chunk within D2
    const int b = (int)(r >> 12);

    const float4 w = g_knnw[r];
    const int4  ii = g_knni[r];
    const float* F = g_f2t + (size_t)b * GPTS * D2;
    const float4* p0 = (const float4*)(F + (size_t)ii.x * D2);
    const float4* p1 = (const float4*)(F + (size_t)ii.y * D2);
    const float4* p2 = (const float4*)(F + (size_t)ii.z * D2);

    float4 a0 = p0[2 * c], a1 = p0[2 * c + 1];
    float4 b0 = p1[2 * c], b1 = p1[2 * c + 1];
    float4 g0 = p2[2 * c], g1 = p2[2 * c + 1];
    float v[8];
    v[0] = w.x * a0.x + w.y * b0.x + w.z * g0.x;
    v[1] = w.x * a0.y + w.y * b0.y + w.z * g0.y;
    v[2] = w.x * a0.z + w.y * b0.z + w.z * g0.z;
    v[3] = w.x * a0.w + w.y * b0.w + w.z * g0.w;
    v[4] = w.x * a1.x + w.y * b1.x + w.z * g1.x;
    v[5] = w.x * a1.y + w.y * b1.y + w.z * g1.y;
    v[6] = w.x * a1.z + w.y * b1.z + w.z * g1.z;
    v[7] = w.x * a1.w + w.y * b1.w + w.z * g1.w;
    pack8_store(v, g_X1 + r * (CIN / 8) + D1 / 8 + c);
}

// ======================= HMMA GEMM (pure fp16, 3-stage pipeline) ============
// C[m][n] = Wh*Xh per K32 chunk (single fp16 product; error ~4.6e-4 rel).
// CTA tile 128(M)x128(N), 3-stage cp.async, one __syncthreads per chunk.
// 8 warps = 2(M)x4(N). LAYER1 -> g_Y1t[n][m]; LAYER2 -> out. BN stats fused.
template <int LAYER>
__global__ void __launch_bounds__(256, 2)
gemm_mma_kernel(const float* __restrict__ bias, float* __restrict__ outp) {
    constexpr int K0 = (LAYER == 1) ? CIN : CH;
    constexpr int NC = K0 / 32;

    const __half* Wh = (LAYER == 1) ? (const __half*)g_W1h : (const __half*)g_W2h;
    const __half* Xh = (LAYER == 1) ? (const __half*)g_X1 : (const __half*)g_X2;
    float* gsum  = (LAYER == 1) ? g_sum1 : g_sum2;
    float* gsq   = (LAYER == 1) ? g_sumsq1 : g_sumsq2;

    __shared__ __align__(16) __half sA[3][128 * SROW];
    __shared__ __align__(16) __half sB[3][128 * SROW];

    const int tid  = threadIdx.x;
    const int wid  = tid >> 5, lane = tid & 31;
    const int tg   = lane >> 2;            // groupID (0..7)
    const int tig  = lane & 3;             // threadID_in_group (0..3)
    const size_t r0 = (size_t)blockIdx.x * 128;   // X row block
    const int m0 = blockIdx.y * 128;              // W row block
    const int wm = (wid & 1) * 64;
    const int wn = (wid >> 1) * 32;

    const uint32_t aA = smem_u32(sA);
    const uint32_t aB = smem_u32(sB);
    const int ldr  = tid >> 2;             // load row (0..63), +64 second half
    const int ldch = tid & 3;              // 16B chunk in row (32 cols = 4)
    const uint32_t ldoff = (uint32_t)(ldr * SROW * 2 + ldch * 16);

    float acc[4][4][4];
    #pragma unroll
    for (int i = 0; i < 4; ++i)
        #pragma unroll
        for (int j = 0; j < 4; ++j)
            #pragma unroll
            for (int k = 0; k < 4; ++k) acc[i][j][k] = 0.f;

    auto issue = [&](int c, int st) {
        const int kk = c * 32;
        const uint32_t so = (uint32_t)st * TILEB + ldoff;
        #pragma unroll
        for (int i = 0; i < 2; ++i) {
            const int r = ldr + i * 64;
            const uint32_t d = so + (uint32_t)(i * 64 * SROW * 2);
            CPA16(aA + d, Wh + (size_t)(m0 + r) * K0 + kk + ldch * 8);
            CPA16(aB + d, Xh + (r0 + r) * K0 + kk + ldch * 8);
        }
        CP_COMMIT();
    };

    issue(0, 0);
    if (NC > 1) issue(1, 1);
    for (int c = 0; c < NC; ++c) {
        if (c + 1 < NC) CP_WAIT1(); else CP_WAIT0();
        __syncthreads();
        if (c + 2 < NC) issue(c + 2, (c + 2) % 3);

        const int st = c % 3;
        const __half* A = sA[st];
        const __half* B = sB[st];
        #pragma unroll
        for (int ks = 0; ks < 2; ++ks) {      // k16 steps within 32-chunk
            const int kb = ks * 16;
            int rb[4], ra0[4], ra1[4];
            #pragma unroll
            for (int ni = 0; ni < 4; ++ni) rb[ni] = (wn + ni * 8 + tg) * SROW;
            #pragma unroll
            for (int mi = 0; mi < 4; ++mi) {
                ra0[mi] = (wm + mi * 16 + tg) * SROW;
                ra1[mi] = ra0[mi] + 8 * SROW;
            }
            uint32_t bh[4][2], ah[4][4];
            #pragma unroll
            for (int ni = 0; ni < 4; ++ni) {
                bh[ni][0] = *(const uint32_t*)(&B[rb[ni] + kb + 2 * tig]);
                bh[ni][1] = *(const uint32_t*)(&B[rb[ni] + kb + 8 + 2 * tig]);
            }
            #pragma unroll
            for (int mi = 0; mi < 4; ++mi) {
                ah[mi][0] = *(const uint32_t*)(&A[ra0[mi] + kb + 2 * tig]);
                ah[mi][1] = *(const uint32_t*)(&A[ra1[mi] + kb + 2 * tig]);
                ah[mi][2] = *(const uint32_t*)(&A[ra0[mi] + kb + 8 + 2 * tig]);
                ah[mi][3] = *(const uint32_t*)(&A[ra1[mi] + kb + 8 + 2 * tig]);
            }
            #pragma unroll
            for (int mi = 0; mi < 4; ++mi)
                #pragma unroll
                for (int ni = 0; ni < 4; ++ni)
                    mma16816(acc[mi][ni], ah[mi][0], ah[mi][1], ah[mi][2], ah[mi][3],
                             bh[ni][0], bh[ni][1]);
        }
    }
    __syncthreads();

    // epilogue: store + fused BN stats
    const int bb = (int)(r0 >> 12);            // batch (LAYER2)
    const int n0 = (int)(r0 & (NPTS - 1));     // n offset within batch
    #pragma unroll
    for (int mi = 0; mi < 4; ++mi) {
        const int mg0 = m0 + wm + mi * 16 + tg;
        const int mg1 = mg0 + 8;
        const float bv0 = bias[mg0];
        const float bv1 = bias[mg1];
        float s0 = 0.f, q0 = 0.f, s1 = 0.f, q1 = 0.f;
        #pragma unroll
        for (int ni = 0; ni < 4; ++ni) {
            const float v00 = acc[mi][ni][0] + bv0;
            const float v01 = acc[mi][ni][1] + bv0;
            const float v10 = acc[mi][ni][2] + bv1;
            const float v11 = acc[mi][ni][3] + bv1;
            if (LAYER == 1) {
                const size_t n = r0 + wn + ni * 8 + 2 * tig;
                g_Y1t[n * 256 + mg0]       = v00;
                g_Y1t[(n + 1) * 256 + mg0] = v01;
                g_Y1t[n * 256 + mg1]       = v10;
                g_Y1t[(n + 1) * 256 + mg1] = v11;
            } else {
                const int nloc = n0 + wn + ni * 8 + 2 * tig;
                *(float2*)(outp + ((size_t)bb * 256 + mg0) * NPTS + nloc) =
                    make_float2(v00, v01);
                *(float2*)(outp + ((size_t)bb * 256 + mg1) * NPTS + nloc) =
                    make_float2(v10, v11);
            }
            s0 += v00 + v01; q0 += v00 * v00 + v01 * v01;
            s1 += v10 + v11; q1 += v10 * v10 + v11 * v11;
        }
        #pragma unroll
        for (int off = 1; off <= 2; off <<= 1) {
            s0 += __shfl_xor_sync(0xffffffffu, s0, off);
            q0 += __shfl_xor_sync(0xffffffffu, q0, off);
            s1 += __shfl_xor_sync(0xffffffffu, s1, off);
            q1 += __shfl_xor_sync(0xffffffffu, q1, off);
        }
        if (tig == 0) {
            atomicAdd(&gsum[mg0], s0); atomicAdd(&gsq[mg0], q0);
            atomicAdd(&gsum[mg1], s1); atomicAdd(&gsq[mg1], q1);
        }
    }
}

// ======================= finalize / fold ====================================
template <int LAYER>
__global__ void finalize_kernel(const float* __restrict__ gamma,
                                const float* __restrict__ beta) {
    const float* gsum = (LAYER == 1) ? g_sum1 : g_sum2;
    const float* gsq  = (LAYER == 1) ? g_sumsq1 : g_sumsq2;
    float* scale      = (LAYER == 1) ? g_scale1 : g_scale2;
    float* shift      = (LAYER == 1) ? g_shift1 : g_shift2;
    const int c = threadIdx.x;
    const float inv = 1.0f / (float)((size_t)NT);
    float m  = gsum[c] * inv;
    float v  = fmaxf(gsq[c] * inv - m * m, 0.f);
    float sc = gamma[c] * rsqrtf(v + BN_EPS);
    scale[c] = sc;
    shift[c] = beta[c] - m * sc;
}

// BN1 + ReLU + fp16 pack: Y1t [row][256] -> X2 [row][256]
__global__ void convert2_kernel() {
    const int gid = blockIdx.x * 256 + threadIdx.x;       // one per 8 channels
    const size_t r = (size_t)(gid >> 5);
    const int c0 = (gid & 31) * 8;
    const float* p = g_Y1t + r * 256 + c0;
    float4 a = *(const float4*)(p);
    float4 b = *(const float4*)(p + 4);
    float4 s0 = *(const float4*)(g_scale1 + c0);
    float4 s1 = *(const float4*)(g_scale1 + c0 + 4);
    float4 t0 = *(const float4*)(g_shift1 + c0);
    float4 t1 = *(const float4*)(g_shift1 + c0 + 4);
    float v[8];
    v[0] = fmaxf(fmaf(a.x, s0.x, t0.x), 0.f);
    v[1] = fmaxf(fmaf(a.y, s0.y, t0.y), 0.f);
    v[2] = fmaxf(fmaf(a.z, s0.z, t0.z), 0.f);
    v[3] = fmaxf(fmaf(a.w, s0.w, t0.w), 0.f);
    v[4] = fmaxf(fmaf(b.x, s1.x, t1.x), 0.f);
    v[5] = fmaxf(fmaf(b.y, s1.y, t1.y), 0.f);
    v[6] = fmaxf(fmaf(b.z, s1.z, t1.z), 0.f);
    v[7] = fmaxf(fmaf(b.w, s1.w, t1.w), 0.f);
    pack8_store(v, g_X2 + (r * 256 + c0) / 8);
}

// final: BN2 + ReLU in place on out [b][m][n]
__global__ void apply2_kernel(float* __restrict__ out) {
    const int i4 = blockIdx.x * 256 + threadIdx.x;   // float4 index
    const int c  = (i4 >> 10) & 255;                 // NPTS/4 = 1024 f4 per row
    const float s = g_scale2[c], t = g_shift2[c];
    float4 v = ((float4*)out)[i4];
    v.x = fmaxf(fmaf(v.x, s, t), 0.f);
    v.y = fmaxf(fmaf(v.y, s, t), 0.f);
    v.z = fmaxf(fmaf(v.z, s, t), 0.f);
    v.w = fmaxf(fmaf(v.w, s, t), 0.f);
    ((float4*)out)[i4] = v;
}

// ======================= launch =============================================
extern "C" void kernel_launch(void* const* d_in, const int* in_sizes, int n_in,
                              void* d_out, int out_size) {
    const float* feature1 = (const float*)d_in[0];
    const float* coord1   = (const float*)d_in[1];
    const float* feature2 = (const float*)d_in[2];
    const float* coord2   = (const float*)d_in[3];
    const float* W1 = (const float*)d_in[4];
    const float* b1 = (const float*)d_in[5];
    const float* gamma1 = (const float*)d_in[6];
    const float* beta1  = (const float*)d_in[7];
    const float* W2 = (const float*)d_in[8];
    const float* b2 = (const float*)d_in[9];
    const float* gamma2 = (const float*)d_in[10];
    const float* beta2  = (const float*)d_in[11];
    float* out = (float*)d_out;

    init_kernel<<<1, 256>>>();
    convert_w_kernel<<<(CH * CIN + COUT * CH + 255) / 256, 256>>>(W1, W2);
    transpose_f2_kernel<<<dim3(GPTS / 32, D2 / 32, BATCH), dim3(32, 8)>>>(feature2);
    transpose_f1_kernel<<<dim3(NPTS / 32, D1 / 32, BATCH), dim3(32, 8)>>>(feature1);
    knn_search_kernel<<<dim3(NPTS / 64, BATCH), 256>>>(coord1, coord2);
    knn_gather_kernel<<<NT * 32 / 256, 256>>>();

    gemm_mma_kernel<1><<<dim3(NT / 128, 2), 256>>>(b1, nullptr);
    finalize_kernel<1><<<1, CH>>>(gamma1, beta1);
    convert2_kernel<<<NT * 32 / 256, 256>>>();

    gemm_mma_kernel<2><<<dim3(NT / 128, 2), 256>>>(b2, out);
    finalize_kernel<2><<<1, COUT>>>(gamma2, beta2);

    apply2_kernel<<<(size_t)BATCH * COUT * NPTS / 4 / 256, 256>>>(out);
}